// round 1
// baseline (speedup 1.0000x reference)
#include <cuda_runtime.h>
#include <cuda_bf16.h>
#include <math.h>

// Problem constants
#define BATCH 2
#define SEQ   2048
#define DMODEL 2048
#define NHEADS 32
#define NKVH   4
#define HDIM   64
#define GQA_REP (NHEADS / NKVH)   // 8
#define MROWS (BATCH * SEQ)       // 4096

// Scratch (device globals; no runtime allocation allowed)
__device__ float g_q[MROWS * NHEADS * HDIM];   // [B*S, 2048]
__device__ float g_k[MROWS * NKVH * HDIM];     // [B*S, 256]
__device__ float g_v[MROWS * NKVH * HDIM];     // [B*S, 256]
__device__ float g_ao[MROWS * NHEADS * HDIM];  // attention output [B*S, 2048]

// ---------------------------------------------------------------------------
// SGEMM: C[M,N] = A[M,K] * B[K,N], row-major, all dims divisible by tiles.
// 128x128 block tile, BK=8, 8x8 per thread, 256 threads.
// ---------------------------------------------------------------------------
#define GBM 128
#define GBN 128
#define GBK 8
#define GTM 8
#define GTN 8

__global__ __launch_bounds__(256, 2)
void sgemm_kernel(int M, int N, int K,
                  const float* __restrict__ A,
                  const float* __restrict__ B,
                  float* __restrict__ C)
{
    __shared__ float As[GBK][GBM];
    __shared__ float Bs[GBK][GBN];

    const int tid = threadIdx.x;
    const int threadCol = tid % (GBN / GTN);  // 0..15
    const int threadRow = tid / (GBN / GTN);  // 0..15

    const float* Ab = A + (size_t)blockIdx.y * GBM * K;
    const float* Bb = B + (size_t)blockIdx.x * GBN;
    float* Cb = C + (size_t)blockIdx.y * GBM * N + (size_t)blockIdx.x * GBN;

    // load indices
    const int innerRowA = tid / (GBK / 4);   // tid/2 : 0..127
    const int innerColA = tid % (GBK / 4);   // 0..1
    const int innerRowB = tid / (GBN / 4);   // tid/32 : 0..7
    const int innerColB = tid % (GBN / 4);   // 0..31

    float acc[GTM][GTN] = {};
    float regM[GTM], regN[GTN];

    for (int k0 = 0; k0 < K; k0 += GBK) {
        float4 a = *(const float4*)(Ab + (size_t)innerRowA * K + k0 + innerColA * 4);
        As[innerColA * 4 + 0][innerRowA] = a.x;
        As[innerColA * 4 + 1][innerRowA] = a.y;
        As[innerColA * 4 + 2][innerRowA] = a.z;
        As[innerColA * 4 + 3][innerRowA] = a.w;
        *(float4*)(&Bs[innerRowB][innerColB * 4]) =
            *(const float4*)(Bb + (size_t)(k0 + innerRowB) * N + innerColB * 4);
        __syncthreads();

        #pragma unroll
        for (int k = 0; k < GBK; k++) {
            #pragma unroll
            for (int i = 0; i < GTM; i++) regM[i] = As[k][threadRow * GTM + i];
            #pragma unroll
            for (int j = 0; j < GTN; j++) regN[j] = Bs[k][threadCol * GTN + j];
            #pragma unroll
            for (int i = 0; i < GTM; i++)
                #pragma unroll
                for (int j = 0; j < GTN; j++)
                    acc[i][j] += regM[i] * regN[j];
        }
        __syncthreads();
    }

    #pragma unroll
    for (int i = 0; i < GTM; i++) {
        float4 v0 = make_float4(acc[i][0], acc[i][1], acc[i][2], acc[i][3]);
        float4 v1 = make_float4(acc[i][4], acc[i][5], acc[i][6], acc[i][7]);
        float* crow = Cb + (size_t)(threadRow * GTM + i) * N + threadCol * GTN;
        *(float4*)(crow)     = v0;
        *(float4*)(crow + 4) = v1;
    }
}

// ---------------------------------------------------------------------------
// RoPE: in-place on tensor [B*S, nheads*HDIM]; freqs_cis is [S, 32, 2].
// One thread per (row, head, pair).
// ---------------------------------------------------------------------------
__global__ void rope_kernel(float* __restrict__ t,
                            const float* __restrict__ freqs,
                            int nheads, int total_pairs)
{
    int idx = blockIdx.x * blockDim.x + threadIdx.x;
    if (idx >= total_pairs) return;
    const int ppr = nheads * (HDIM / 2);
    int row = idx / ppr;              // b*SEQ + s
    int pr  = idx % ppr;
    int hh  = pr / (HDIM / 2);
    int i   = pr % (HDIM / 2);
    int s   = row % SEQ;
    float c  = freqs[s * HDIM + i * 2 + 0];
    float sn = freqs[s * HDIM + i * 2 + 1];
    float* p = t + (size_t)row * (nheads * HDIM) + hh * HDIM + i * 2;
    float xr = p[0], xi = p[1];
    p[0] = xr * c - xi * sn;
    p[1] = xr * sn + xi * c;
}

// ---------------------------------------------------------------------------
// Flash attention (fp32, causal, GQA).
// Block: 256 threads handles 64 queries x full HDIM=64 for one (b, h).
// Iterates key tiles of 64 up to the diagonal with online softmax.
// Dynamic smem layout: Qs[64][65] Ks[64][65] Vs[64][65] Ss[64][65] m/l/alpha[64]
// ---------------------------------------------------------------------------
#define AQ 64
#define AK 64
#define APAD 65

__global__ __launch_bounds__(256, 3)
void attn_kernel(const float* __restrict__ Q,
                 const float* __restrict__ K,
                 const float* __restrict__ V,
                 float* __restrict__ O)
{
    extern __shared__ float sm[];
    float* Qs = sm;                       // AQ*APAD
    float* Ks = sm + AQ * APAD;           // AK*APAD
    float* Vs = sm + 2 * AQ * APAD;       // AK*APAD
    float* Ss = sm + 3 * AQ * APAD;       // AQ*APAD
    float* mS = sm + 4 * AQ * APAD;       // 64
    float* lS = mS + AQ;                  // 64
    float* aS = mS + 2 * AQ;              // 64

    const int tid = threadIdx.x;
    const int qt = blockIdx.x;
    const int h  = blockIdx.y;
    const int b  = blockIdx.z;
    const int kvh = h / GQA_REP;

    const float* Qb = Q + ((size_t)(b * SEQ + qt * AQ)) * (NHEADS * HDIM) + h * HDIM;
    const float scale = 0.125f;  // 1/sqrt(64)

    // load Q tile (scaled)
    for (int e = tid; e < AQ * (HDIM / 4); e += 256) {
        int r = e / (HDIM / 4), c4 = e % (HDIM / 4);
        float4 v = *(const float4*)(Qb + (size_t)r * (NHEADS * HDIM) + c4 * 4);
        Qs[r * APAD + c4 * 4 + 0] = v.x * scale;
        Qs[r * APAD + c4 * 4 + 1] = v.y * scale;
        Qs[r * APAD + c4 * 4 + 2] = v.z * scale;
        Qs[r * APAD + c4 * 4 + 3] = v.w * scale;
    }
    if (tid < AQ) { mS[tid] = -3.4e38f; lS[tid] = 0.0f; }

    const int rowBase = (tid / 16) * 4;
    const int colBase = (tid % 16) * 4;
    float Oa[4][4] = {};

    __syncthreads();

    for (int kt = 0; kt <= qt; kt++) {
        // load K, V tiles
        const float* Kb = K + ((size_t)(b * SEQ + kt * AK)) * (NKVH * HDIM) + kvh * HDIM;
        const float* Vb = V + ((size_t)(b * SEQ + kt * AK)) * (NKVH * HDIM) + kvh * HDIM;
        for (int e = tid; e < AK * (HDIM / 4); e += 256) {
            int r = e / (HDIM / 4), c4 = e % (HDIM / 4);
            float4 kv = *(const float4*)(Kb + (size_t)r * (NKVH * HDIM) + c4 * 4);
            float4 vv = *(const float4*)(Vb + (size_t)r * (NKVH * HDIM) + c4 * 4);
            Ks[r * APAD + c4 * 4 + 0] = kv.x;
            Ks[r * APAD + c4 * 4 + 1] = kv.y;
            Ks[r * APAD + c4 * 4 + 2] = kv.z;
            Ks[r * APAD + c4 * 4 + 3] = kv.w;
            Vs[r * APAD + c4 * 4 + 0] = vv.x;
            Vs[r * APAD + c4 * 4 + 1] = vv.y;
            Vs[r * APAD + c4 * 4 + 2] = vv.z;
            Vs[r * APAD + c4 * 4 + 3] = vv.w;
        }
        __syncthreads();

        // S = Q @ K^T for this 64x64 tile
        float acc[4][4] = {};
        #pragma unroll 4
        for (int d = 0; d < HDIM; d++) {
            float q0 = Qs[(rowBase + 0) * APAD + d];
            float q1 = Qs[(rowBase + 1) * APAD + d];
            float q2 = Qs[(rowBase + 2) * APAD + d];
            float q3 = Qs[(rowBase + 3) * APAD + d];
            float k0 = Ks[(colBase + 0) * APAD + d];
            float k1 = Ks[(colBase + 1) * APAD + d];
            float k2 = Ks[(colBase + 2) * APAD + d];
            float k3 = Ks[(colBase + 3) * APAD + d];
            acc[0][0] += q0 * k0; acc[0][1] += q0 * k1; acc[0][2] += q0 * k2; acc[0][3] += q0 * k3;
            acc[1][0] += q1 * k0; acc[1][1] += q1 * k1; acc[1][2] += q1 * k2; acc[1][3] += q1 * k3;
            acc[2][0] += q2 * k0; acc[2][1] += q2 * k1; acc[2][2] += q2 * k2; acc[2][3] += q2 * k3;
            acc[3][0] += q3 * k0; acc[3][1] += q3 * k1; acc[3][2] += q3 * k2; acc[3][3] += q3 * k3;
        }
        const bool diag = (kt == qt);
        #pragma unroll
        for (int i = 0; i < 4; i++)
            #pragma unroll
            for (int j = 0; j < 4; j++) {
                float s = acc[i][j];
                if (diag && (colBase + j > rowBase + i)) s = -1e30f;
                Ss[(rowBase + i) * APAD + (colBase + j)] = s;
            }
        __syncthreads();

        // online softmax, one thread per row
        if (tid < AQ) {
            float mOld = mS[tid];
            float mNew = mOld;
            #pragma unroll 8
            for (int j = 0; j < AK; j++) mNew = fmaxf(mNew, Ss[tid * APAD + j]);
            float al = __expf(mOld - mNew);
            float l = lS[tid] * al;
            #pragma unroll 8
            for (int j = 0; j < AK; j++) {
                float p = __expf(Ss[tid * APAD + j] - mNew);
                Ss[tid * APAD + j] = p;
                l += p;
            }
            mS[tid] = mNew; lS[tid] = l; aS[tid] = al;
        }
        __syncthreads();

        // O = O*alpha + P @ V
        float a0 = aS[rowBase + 0], a1 = aS[rowBase + 1];
        float a2 = aS[rowBase + 2], a3 = aS[rowBase + 3];
        #pragma unroll
        for (int j = 0; j < 4; j++) {
            Oa[0][j] *= a0; Oa[1][j] *= a1; Oa[2][j] *= a2; Oa[3][j] *= a3;
        }
        #pragma unroll 4
        for (int kk = 0; kk < AK; kk++) {
            float p0 = Ss[(rowBase + 0) * APAD + kk];
            float p1 = Ss[(rowBase + 1) * APAD + kk];
            float p2 = Ss[(rowBase + 2) * APAD + kk];
            float p3 = Ss[(rowBase + 3) * APAD + kk];
            float v0 = Vs[kk * APAD + colBase + 0];
            float v1 = Vs[kk * APAD + colBase + 1];
            float v2 = Vs[kk * APAD + colBase + 2];
            float v3 = Vs[kk * APAD + colBase + 3];
            Oa[0][0] += p0 * v0; Oa[0][1] += p0 * v1; Oa[0][2] += p0 * v2; Oa[0][3] += p0 * v3;
            Oa[1][0] += p1 * v0; Oa[1][1] += p1 * v1; Oa[1][2] += p1 * v2; Oa[1][3] += p1 * v3;
            Oa[2][0] += p2 * v0; Oa[2][1] += p2 * v1; Oa[2][2] += p2 * v2; Oa[2][3] += p2 * v3;
            Oa[3][0] += p3 * v0; Oa[3][1] += p3 * v1; Oa[3][2] += p3 * v2; Oa[3][3] += p3 * v3;
        }
        __syncthreads();  // protect Ks/Vs/Ss before next tile load
    }

    // epilogue: O / l
    float il0 = 1.0f / lS[rowBase + 0];
    float il1 = 1.0f / lS[rowBase + 1];
    float il2 = 1.0f / lS[rowBase + 2];
    float il3 = 1.0f / lS[rowBase + 3];
    float* Ob = O + ((size_t)(b * SEQ + qt * AQ)) * (NHEADS * HDIM) + h * HDIM;
    float il[4] = {il0, il1, il2, il3};
    #pragma unroll
    for (int i = 0; i < 4; i++) {
        float4 v = make_float4(Oa[i][0] * il[i], Oa[i][1] * il[i],
                               Oa[i][2] * il[i], Oa[i][3] * il[i]);
        *(float4*)(Ob + (size_t)(rowBase + i) * (NHEADS * HDIM) + colBase) = v;
    }
}

// ---------------------------------------------------------------------------
// launch
// ---------------------------------------------------------------------------
extern "C" void kernel_launch(void* const* d_in, const int* in_sizes, int n_in,
                              void* d_out, int out_size)
{
    const float* x     = (const float*)d_in[0];
    const float* freqs = (const float*)d_in[1];
    // d_in[2] is the additive mask — equivalent to causal; handled in-kernel.
    const float* wq    = (const float*)d_in[3];
    const float* wk    = (const float*)d_in[4];
    const float* wv    = (const float*)d_in[5];
    const float* wo    = (const float*)d_in[6];
    float* out = (float*)d_out;

    static float *gq = nullptr, *gk = nullptr, *gv = nullptr, *gao = nullptr;
    static int attn_smem = 0;
    if (!gq) {
        cudaGetSymbolAddress((void**)&gq,  g_q);
        cudaGetSymbolAddress((void**)&gk,  g_k);
        cudaGetSymbolAddress((void**)&gv,  g_v);
        cudaGetSymbolAddress((void**)&gao, g_ao);
        attn_smem = (4 * AQ * APAD + 3 * AQ) * (int)sizeof(float);
        cudaFuncSetAttribute(attn_kernel, cudaFuncAttributeMaxDynamicSharedMemorySize,
                             attn_smem);
    }

    // QKV projections
    sgemm_kernel<<<dim3(DMODEL / GBN, MROWS / GBM), 256>>>(MROWS, DMODEL, DMODEL, x, wq, gq);
    sgemm_kernel<<<dim3((NKVH * HDIM) / GBN, MROWS / GBM), 256>>>(MROWS, NKVH * HDIM, DMODEL, x, wk, gk);
    sgemm_kernel<<<dim3((NKVH * HDIM) / GBN, MROWS / GBM), 256>>>(MROWS, NKVH * HDIM, DMODEL, x, wv, gv);

    // RoPE on Q and K
    {
        int pq = MROWS * NHEADS * (HDIM / 2);
        int pk = MROWS * NKVH * (HDIM / 2);
        rope_kernel<<<(pq + 255) / 256, 256>>>(gq, freqs, NHEADS, pq);
        rope_kernel<<<(pk + 255) / 256, 256>>>(gk, freqs, NKVH, pk);
    }

    // attention
    attn_kernel<<<dim3(SEQ / AQ, NHEADS, BATCH), 256, attn_smem>>>(gq, gk, gv, gao);

    // output projection
    sgemm_kernel<<<dim3(DMODEL / GBN, MROWS / GBM), 256>>>(MROWS, DMODEL, DMODEL, gao, wo, out);
}

// round 3
// speedup vs baseline: 1.8081x; 1.8081x over previous
#include <cuda_runtime.h>
#include <cuda_bf16.h>
#include <math.h>
#include <stdint.h>

// Problem constants
#define BATCH 2
#define SEQ   2048
#define DMODEL 2048
#define NHEADS 32
#define NKVH   4
#define HDIM   64
#define GQA_REP (NHEADS / NKVH)   // 8
#define MROWS (BATCH * SEQ)       // 4096

// Scratch (device globals; no runtime allocation allowed)
__device__ float g_q[MROWS * NHEADS * HDIM];   // [B*S, 2048]
__device__ float g_k[MROWS * NKVH * HDIM];     // [B*S, 256]
__device__ float g_v[MROWS * NKVH * HDIM];     // [B*S, 256]
__device__ float g_ao[MROWS * NHEADS * HDIM];  // attention output [B*S, 2048]
__device__ float g_wqT[DMODEL * NHEADS * HDIM];  // [2048,2048] (N,K) k-major
__device__ float g_wkT[DMODEL * NKVH * HDIM];    // [256,2048]
__device__ float g_wvT[DMODEL * NKVH * HDIM];    // [256,2048]
__device__ float g_woT[DMODEL * NHEADS * HDIM];  // [2048,2048]

// ---------------------------------------------------------------------------
// Weight transpose: in [R,C] row-major -> out [C,R] row-major
// ---------------------------------------------------------------------------
__global__ void transpose_kernel(const float* __restrict__ in, float* __restrict__ out,
                                 int R, int C)
{
    __shared__ float t[32][33];
    int c0 = blockIdx.x * 32, r0 = blockIdx.y * 32;
    int x = threadIdx.x, y = threadIdx.y;  // 32 x 8
    #pragma unroll
    for (int j = 0; j < 4; j++)
        t[y + 8 * j][x] = in[(size_t)(r0 + y + 8 * j) * C + c0 + x];
    __syncthreads();
    #pragma unroll
    for (int j = 0; j < 4; j++)
        out[(size_t)(c0 + y + 8 * j) * R + r0 + x] = t[x][y + 8 * j];
}

// ---------------------------------------------------------------------------
// tf32 mma.sync GEMM: C[M,N] = A[M,K] @ BT[N,K]^T (both k-contiguous).
// CTA tile 128x128, BK=32, 256 threads = 8 warps (2M x 4N), warp tile 64x32.
// Fragments: mma.sync.aligned.m16n8k8.row.col.f32.tf32.tf32.f32
// Smem: K-major tiles [128][36] (stride 36 -> conflict-free fragment reads).
// Double-buffered smem; global loads register-staged ahead of compute.
// ---------------------------------------------------------------------------
#define MM_BM 128
#define MM_BN 128
#define MM_BK 32
#define MM_STR 36
#define MM_THREADS 256
#define MM_TILE_U32 (MM_BM * MM_STR)          // 4608 u32 per tile
#define MM_SMEM_BYTES (4 * MM_TILE_U32 * 4)   // A0,B0,A1,B1 = 73728 B

__device__ __forceinline__ uint32_t f2tf32(float f) {
    uint32_t u;
    asm("cvt.rna.tf32.f32 %0, %1;" : "=r"(u) : "f"(f));
    return u;
}

__device__ __forceinline__ void mma_tf32(float* d, const uint32_t* a, const uint32_t* b) {
    asm volatile(
        "mma.sync.aligned.m16n8k8.row.col.f32.tf32.tf32.f32 "
        "{%0,%1,%2,%3}, {%4,%5,%6,%7}, {%8,%9}, {%0,%1,%2,%3};"
        : "+f"(d[0]), "+f"(d[1]), "+f"(d[2]), "+f"(d[3])
        : "r"(a[0]), "r"(a[1]), "r"(a[2]), "r"(a[3]), "r"(b[0]), "r"(b[1]));
}

__global__ __launch_bounds__(MM_THREADS)
void mma_gemm_kernel(int M, int N, int K,
                     const float* __restrict__ A,
                     const float* __restrict__ BT,
                     float* __restrict__ C)
{
    extern __shared__ uint32_t sm_u[];
    uint32_t* sA[2] = {sm_u, sm_u + 2 * MM_TILE_U32};
    uint32_t* sB[2] = {sm_u + MM_TILE_U32, sm_u + 3 * MM_TILE_U32};

    const int tid  = threadIdx.x;
    const int warp = tid >> 5;
    const int lane = tid & 31;
    const int g    = lane >> 2;   // 0..7
    const int tig  = lane & 3;    // 0..3

    const int wm = (warp >> 2) * 64;  // 0 or 64
    const int wn = (warp & 3) * 32;   // 0,32,64,96

    const int m0 = blockIdx.y * MM_BM;
    const int n0 = blockIdx.x * MM_BN;

    // loader indices: over j=0..3, row = (tid>>3)+32j, 4 floats at col c4*4
    const int lrow = tid >> 3;   // 0..31
    const int lc4  = tid & 7;    // 0..7

    const float* Abase = A  + (size_t)(m0 + lrow) * K + lc4 * 4;
    const float* Bbase = BT + (size_t)(n0 + lrow) * K + lc4 * 4;

    float acc[4][4][4] = {};   // [mtile16][ntile8][reg]
    float4 ra[4], rb[4];

    const int NC = K / MM_BK;

    // ---- load chunk 0 into regs, store to buf 0
    #pragma unroll
    for (int j = 0; j < 4; j++) {
        ra[j] = *(const float4*)(Abase + (size_t)(j * 32) * K);
        rb[j] = *(const float4*)(Bbase + (size_t)(j * 32) * K);
    }
    #pragma unroll
    for (int j = 0; j < 4; j++) {
        int off = (lrow + j * 32) * MM_STR + lc4 * 4;
        *(uint4*)(sA[0] + off) = make_uint4(f2tf32(ra[j].x), f2tf32(ra[j].y),
                                            f2tf32(ra[j].z), f2tf32(ra[j].w));
        *(uint4*)(sB[0] + off) = make_uint4(f2tf32(rb[j].x), f2tf32(rb[j].y),
                                            f2tf32(rb[j].z), f2tf32(rb[j].w));
    }
    __syncthreads();

    for (int c = 0; c < NC; c++) {
        const int buf = c & 1;

        // issue global loads for next chunk (in flight during compute)
        if (c + 1 < NC) {
            const float* An = Abase + (size_t)(c + 1) * MM_BK;
            const float* Bn = Bbase + (size_t)(c + 1) * MM_BK;
            #pragma unroll
            for (int j = 0; j < 4; j++) {
                ra[j] = *(const float4*)(An + (size_t)(j * 32) * K);
                rb[j] = *(const float4*)(Bn + (size_t)(j * 32) * K);
            }
        }

        // compute on current buffer
        const uint32_t* As = sA[buf];
        const uint32_t* Bs = sB[buf];
        #pragma unroll
        for (int ks = 0; ks < 4; ks++) {
            const int k0 = ks * 8;
            uint32_t af[4][4], bf[4][2];
            #pragma unroll
            for (int mt = 0; mt < 4; mt++) {
                const int row = wm + mt * 16;
                af[mt][0] = As[(row + g) * MM_STR + k0 + tig];
                af[mt][1] = As[(row + g + 8) * MM_STR + k0 + tig];
                af[mt][2] = As[(row + g) * MM_STR + k0 + tig + 4];
                af[mt][3] = As[(row + g + 8) * MM_STR + k0 + tig + 4];
            }
            #pragma unroll
            for (int nt = 0; nt < 4; nt++) {
                const int col = wn + nt * 8 + g;
                bf[nt][0] = Bs[col * MM_STR + k0 + tig];
                bf[nt][1] = Bs[col * MM_STR + k0 + tig + 4];
            }
            #pragma unroll
            for (int mt = 0; mt < 4; mt++)
                #pragma unroll
                for (int nt = 0; nt < 4; nt++)
                    mma_tf32(acc[mt][nt], af[mt], bf[nt]);
        }

        // stage next chunk into the other buffer
        if (c + 1 < NC) {
            __syncthreads();
            uint32_t* Ad = sA[buf ^ 1];
            uint32_t* Bd = sB[buf ^ 1];
            #pragma unroll
            for (int j = 0; j < 4; j++) {
                int off = (lrow + j * 32) * MM_STR + lc4 * 4;
                *(uint4*)(Ad + off) = make_uint4(f2tf32(ra[j].x), f2tf32(ra[j].y),
                                                 f2tf32(ra[j].z), f2tf32(ra[j].w));
                *(uint4*)(Bd + off) = make_uint4(f2tf32(rb[j].x), f2tf32(rb[j].y),
                                                 f2tf32(rb[j].z), f2tf32(rb[j].w));
            }
            __syncthreads();
        }
    }

    // epilogue: direct global stores (float2 per c-pair)
    #pragma unroll
    for (int mt = 0; mt < 4; mt++) {
        const int row = m0 + wm + mt * 16 + g;
        #pragma unroll
        for (int nt = 0; nt < 4; nt++) {
            const int col = n0 + wn + nt * 8 + tig * 2;
            *(float2*)(C + (size_t)row * N + col) =
                make_float2(acc[mt][nt][0], acc[mt][nt][1]);
            *(float2*)(C + (size_t)(row + 8) * N + col) =
                make_float2(acc[mt][nt][2], acc[mt][nt][3]);
        }
    }
}

// ---------------------------------------------------------------------------
// RoPE: in-place on tensor [B*S, nheads*HDIM]; freqs_cis is [S, 32, 2].
// ---------------------------------------------------------------------------
__global__ void rope_kernel(float* __restrict__ t,
                            const float* __restrict__ freqs,
                            int nheads, int total_pairs)
{
    int idx = blockIdx.x * blockDim.x + threadIdx.x;
    if (idx >= total_pairs) return;
    const int ppr = nheads * (HDIM / 2);
    int row = idx / ppr;
    int pr  = idx % ppr;
    int hh  = pr / (HDIM / 2);
    int i   = pr % (HDIM / 2);
    int s   = row % SEQ;
    float c  = freqs[s * HDIM + i * 2 + 0];
    float sn = freqs[s * HDIM + i * 2 + 1];
    float* p = t + (size_t)row * (nheads * HDIM) + hh * HDIM + i * 2;
    float xr = p[0], xi = p[1];
    p[0] = xr * c - xi * sn;
    p[1] = xr * sn + xi * c;
}

// ---------------------------------------------------------------------------
// Flash attention (fp32, causal, GQA). Unchanged from round 1 (passing).
// ---------------------------------------------------------------------------
#define AQ 64
#define AK 64
#define APAD 65

__global__ __launch_bounds__(256, 3)
void attn_kernel(const float* __restrict__ Q,
                 const float* __restrict__ K,
                 const float* __restrict__ V,
                 float* __restrict__ O)
{
    extern __shared__ float sm[];
    float* Qs = sm;
    float* Ks = sm + AQ * APAD;
    float* Vs = sm + 2 * AQ * APAD;
    float* Ss = sm + 3 * AQ * APAD;
    float* mS = sm + 4 * AQ * APAD;
    float* lS = mS + AQ;
    float* aS = mS + 2 * AQ;

    const int tid = threadIdx.x;
    const int qt = blockIdx.x;
    const int h  = blockIdx.y;
    const int b  = blockIdx.z;
    const int kvh = h / GQA_REP;

    const float* Qb = Q + ((size_t)(b * SEQ + qt * AQ)) * (NHEADS * HDIM) + h * HDIM;
    const float scale = 0.125f;

    for (int e = tid; e < AQ * (HDIM / 4); e += 256) {
        int r = e / (HDIM / 4), c4 = e % (HDIM / 4);
        float4 v = *(const float4*)(Qb + (size_t)r * (NHEADS * HDIM) + c4 * 4);
        Qs[r * APAD + c4 * 4 + 0] = v.x * scale;
        Qs[r * APAD + c4 * 4 + 1] = v.y * scale;
        Qs[r * APAD + c4 * 4 + 2] = v.z * scale;
        Qs[r * APAD + c4 * 4 + 3] = v.w * scale;
    }
    if (tid < AQ) { mS[tid] = -3.4e38f; lS[tid] = 0.0f; }

    const int rowBase = (tid / 16) * 4;
    const int colBase = (tid % 16) * 4;
    float Oa[4][4] = {};

    __syncthreads();

    for (int kt = 0; kt <= qt; kt++) {
        const float* Kb = K + ((size_t)(b * SEQ + kt * AK)) * (NKVH * HDIM) + kvh * HDIM;
        const float* Vb = V + ((size_t)(b * SEQ + kt * AK)) * (NKVH * HDIM) + kvh * HDIM;
        for (int e = tid; e < AK * (HDIM / 4); e += 256) {
            int r = e / (HDIM / 4), c4 = e % (HDIM / 4);
            float4 kv = *(const float4*)(Kb + (size_t)r * (NKVH * HDIM) + c4 * 4);
            float4 vv = *(const float4*)(Vb + (size_t)r * (NKVH * HDIM) + c4 * 4);
            Ks[r * APAD + c4 * 4 + 0] = kv.x;
            Ks[r * APAD + c4 * 4 + 1] = kv.y;
            Ks[r * APAD + c4 * 4 + 2] = kv.z;
            Ks[r * APAD + c4 * 4 + 3] = kv.w;
            Vs[r * APAD + c4 * 4 + 0] = vv.x;
            Vs[r * APAD + c4 * 4 + 1] = vv.y;
            Vs[r * APAD + c4 * 4 + 2] = vv.z;
            Vs[r * APAD + c4 * 4 + 3] = vv.w;
        }
        __syncthreads();

        float acc[4][4] = {};
        #pragma unroll 4
        for (int d = 0; d < HDIM; d++) {
            float q0 = Qs[(rowBase + 0) * APAD + d];
            float q1 = Qs[(rowBase + 1) * APAD + d];
            float q2 = Qs[(rowBase + 2) * APAD + d];
            float q3 = Qs[(rowBase + 3) * APAD + d];
            float k0 = Ks[(colBase + 0) * APAD + d];
            float k1 = Ks[(colBase + 1) * APAD + d];
            float k2 = Ks[(colBase + 2) * APAD + d];
            float k3 = Ks[(colBase + 3) * APAD + d];
            acc[0][0] += q0 * k0; acc[0][1] += q0 * k1; acc[0][2] += q0 * k2; acc[0][3] += q0 * k3;
            acc[1][0] += q1 * k0; acc[1][1] += q1 * k1; acc[1][2] += q1 * k2; acc[1][3] += q1 * k3;
            acc[2][0] += q2 * k0; acc[2][1] += q2 * k1; acc[2][2] += q2 * k2; acc[2][3] += q2 * k3;
            acc[3][0] += q3 * k0; acc[3][1] += q3 * k1; acc[3][2] += q3 * k2; acc[3][3] += q3 * k3;
        }
        const bool diag = (kt == qt);
        #pragma unroll
        for (int i = 0; i < 4; i++)
            #pragma unroll
            for (int j = 0; j < 4; j++) {
                float s = acc[i][j];
                if (diag && (colBase + j > rowBase + i)) s = -1e30f;
                Ss[(rowBase + i) * APAD + (colBase + j)] = s;
            }
        __syncthreads();

        if (tid < AQ) {
            float mOld = mS[tid];
            float mNew = mOld;
            #pragma unroll 8
            for (int j = 0; j < AK; j++) mNew = fmaxf(mNew, Ss[tid * APAD + j]);
            float al = __expf(mOld - mNew);
            float l = lS[tid] * al;
            #pragma unroll 8
            for (int j = 0; j < AK; j++) {
                float p = __expf(Ss[tid * APAD + j] - mNew);
                Ss[tid * APAD + j] = p;
                l += p;
            }
            mS[tid] = mNew; lS[tid] = l; aS[tid] = al;
        }
        __syncthreads();

        float a0 = aS[rowBase + 0], a1 = aS[rowBase + 1];
        float a2 = aS[rowBase + 2], a3 = aS[rowBase + 3];
        #pragma unroll
        for (int j = 0; j < 4; j++) {
            Oa[0][j] *= a0; Oa[1][j] *= a1; Oa[2][j] *= a2; Oa[3][j] *= a3;
        }
        #pragma unroll 4
        for (int kk = 0; kk < AK; kk++) {
            float p0 = Ss[(rowBase + 0) * APAD + kk];
            float p1 = Ss[(rowBase + 1) * APAD + kk];
            float p2 = Ss[(rowBase + 2) * APAD + kk];
            float p3 = Ss[(rowBase + 3) * APAD + kk];
            float v0 = Vs[kk * APAD + colBase + 0];
            float v1 = Vs[kk * APAD + colBase + 1];
            float v2 = Vs[kk * APAD + colBase + 2];
            float v3 = Vs[kk * APAD + colBase + 3];
            Oa[0][0] += p0 * v0; Oa[0][1] += p0 * v1; Oa[0][2] += p0 * v2; Oa[0][3] += p0 * v3;
            Oa[1][0] += p1 * v0; Oa[1][1] += p1 * v1; Oa[1][2] += p1 * v2; Oa[1][3] += p1 * v3;
            Oa[2][0] += p2 * v0; Oa[2][1] += p2 * v1; Oa[2][2] += p2 * v2; Oa[2][3] += p2 * v3;
            Oa[3][0] += p3 * v0; Oa[3][1] += p3 * v1; Oa[3][2] += p3 * v2; Oa[3][3] += p3 * v3;
        }
        __syncthreads();
    }

    float il[4];
    il[0] = 1.0f / lS[rowBase + 0];
    il[1] = 1.0f / lS[rowBase + 1];
    il[2] = 1.0f / lS[rowBase + 2];
    il[3] = 1.0f / lS[rowBase + 3];
    float* Ob = O + ((size_t)(b * SEQ + qt * AQ)) * (NHEADS * HDIM) + h * HDIM;
    #pragma unroll
    for (int i = 0; i < 4; i++) {
        float4 v = make_float4(Oa[i][0] * il[i], Oa[i][1] * il[i],
                               Oa[i][2] * il[i], Oa[i][3] * il[i]);
        *(float4*)(Ob + (size_t)(rowBase + i) * (NHEADS * HDIM) + colBase) = v;
    }
}

// ---------------------------------------------------------------------------
// launch
// ---------------------------------------------------------------------------
extern "C" void kernel_launch(void* const* d_in, const int* in_sizes, int n_in,
                              void* d_out, int out_size)
{
    const float* x     = (const float*)d_in[0];
    const float* freqs = (const float*)d_in[1];
    // d_in[2] is the additive mask — exactly causal; handled in-kernel.
    const float* wq    = (const float*)d_in[3];
    const float* wk    = (const float*)d_in[4];
    const float* wv    = (const float*)d_in[5];
    const float* wo    = (const float*)d_in[6];
    float* out = (float*)d_out;

    static float *gq = nullptr, *gk = nullptr, *gv = nullptr, *gao = nullptr;
    static float *wqT = nullptr, *wkT = nullptr, *wvT = nullptr, *woT = nullptr;
    static int attn_smem = 0;
    if (!gq) {
        cudaGetSymbolAddress((void**)&gq,  g_q);
        cudaGetSymbolAddress((void**)&gk,  g_k);
        cudaGetSymbolAddress((void**)&gv,  g_v);
        cudaGetSymbolAddress((void**)&gao, g_ao);
        cudaGetSymbolAddress((void**)&wqT, g_wqT);
        cudaGetSymbolAddress((void**)&wkT, g_wkT);
        cudaGetSymbolAddress((void**)&wvT, g_wvT);
        cudaGetSymbolAddress((void**)&woT, g_woT);
        attn_smem = (4 * AQ * APAD + 3 * AQ) * (int)sizeof(float);
        cudaFuncSetAttribute(attn_kernel, cudaFuncAttributeMaxDynamicSharedMemorySize,
                             attn_smem);
        cudaFuncSetAttribute(mma_gemm_kernel, cudaFuncAttributeMaxDynamicSharedMemorySize,
                             MM_SMEM_BYTES);
    }

    // transpose weights to k-major (N,K)
    {
        dim3 blk(32, 8);
        transpose_kernel<<<dim3(DMODEL / 32, DMODEL / 32), blk>>>(wq, wqT, DMODEL, DMODEL);
        transpose_kernel<<<dim3((NKVH * HDIM) / 32, DMODEL / 32), blk>>>(wk, wkT, DMODEL, NKVH * HDIM);
        transpose_kernel<<<dim3((NKVH * HDIM) / 32, DMODEL / 32), blk>>>(wv, wvT, DMODEL, NKVH * HDIM);
        transpose_kernel<<<dim3(DMODEL / 32, DMODEL / 32), blk>>>(wo, woT, DMODEL, DMODEL);
    }

    // QKV projections (tf32 mma)
    mma_gemm_kernel<<<dim3(DMODEL / MM_BN, MROWS / MM_BM), MM_THREADS, MM_SMEM_BYTES>>>(
        MROWS, DMODEL, DMODEL, x, wqT, gq);
    mma_gemm_kernel<<<dim3((NKVH * HDIM) / MM_BN, MROWS / MM_BM), MM_THREADS, MM_SMEM_BYTES>>>(
        MROWS, NKVH * HDIM, DMODEL, x, wkT, gk);
    mma_gemm_kernel<<<dim3((NKVH * HDIM) / MM_BN, MROWS / MM_BM), MM_THREADS, MM_SMEM_BYTES>>>(
        MROWS, NKVH * HDIM, DMODEL, x, wvT, gv);

    // RoPE on Q and K
    {
        int pq = MROWS * NHEADS * (HDIM / 2);
        int pk = MROWS * NKVH * (HDIM / 2);
        rope_kernel<<<(pq + 255) / 256, 256>>>(gq, freqs, NHEADS, pq);
        rope_kernel<<<(pk + 255) / 256, 256>>>(gk, freqs, NKVH, pk);
    }

    // attention
    attn_kernel<<<dim3(SEQ / AQ, NHEADS, BATCH), 256, attn_smem>>>(gq, gk, gv, gao);

    // output projection (tf32 mma)
    mma_gemm_kernel<<<dim3(DMODEL / MM_BN, MROWS / MM_BM), MM_THREADS, MM_SMEM_BYTES>>>(
        MROWS, DMODEL, DMODEL, gao, woT, out);
}

// round 4
// speedup vs baseline: 3.7363x; 2.0664x over previous
#include <cuda_runtime.h>
#include <cuda_bf16.h>
#include <math.h>
#include <stdint.h>

// Problem constants
#define BATCH 2
#define SEQ   2048
#define DMODEL 2048
#define NHEADS 32
#define NKVH   4
#define HDIM   64
#define GQA_REP (NHEADS / NKVH)   // 8
#define MROWS (BATCH * SEQ)       // 4096
#define KVLD  (2 * NKVH * HDIM)   // 512: fused [K|V] row stride

// Scratch (device globals; no runtime allocation allowed)
__device__ float g_q[MROWS * NHEADS * HDIM];    // [4096, 2048]
__device__ float g_kv[MROWS * KVLD];            // [4096, 512]  (K cols 0..255, V cols 256..511)
__device__ float g_ao[MROWS * NHEADS * HDIM];   // [4096, 2048]
__device__ float g_wqT[DMODEL * DMODEL];        // [2048,2048] (N,K) k-major
__device__ float g_wkvT[KVLD * DMODEL];         // [512, 2048] rows 0..255 = wk^T, 256..511 = wv^T
__device__ float g_woT[DMODEL * DMODEL];

// ---------------------------------------------------------------------------
// common helpers
// ---------------------------------------------------------------------------
__device__ __forceinline__ uint32_t f2tf32(float f) {
    uint32_t u;
    asm("cvt.rna.tf32.f32 %0, %1;" : "=r"(u) : "f"(f));
    return u;
}
__device__ __forceinline__ float fexp2(float x) {
    float y;
    asm("ex2.approx.ftz.f32 %0, %1;" : "=f"(y) : "f"(x));
    return y;
}
__device__ __forceinline__ void mma_tf32(float* d, const uint32_t* a, const uint32_t* b) {
    asm volatile(
        "mma.sync.aligned.m16n8k8.row.col.f32.tf32.tf32.f32 "
        "{%0,%1,%2,%3}, {%4,%5,%6,%7}, {%8,%9}, {%0,%1,%2,%3};"
        : "+f"(d[0]), "+f"(d[1]), "+f"(d[2]), "+f"(d[3])
        : "r"(a[0]), "r"(a[1]), "r"(a[2]), "r"(a[3]), "r"(b[0]), "r"(b[1]));
}

// ---------------------------------------------------------------------------
// Weight transpose: in [R,C] row-major -> out [C,R] row-major
// ---------------------------------------------------------------------------
__global__ void transpose_kernel(const float* __restrict__ in, float* __restrict__ out,
                                 int R, int C)
{
    __shared__ float t[32][33];
    int c0 = blockIdx.x * 32, r0 = blockIdx.y * 32;
    int x = threadIdx.x, y = threadIdx.y;  // 32 x 8
    #pragma unroll
    for (int j = 0; j < 4; j++)
        t[y + 8 * j][x] = in[(size_t)(r0 + y + 8 * j) * C + c0 + x];
    __syncthreads();
    #pragma unroll
    for (int j = 0; j < 4; j++)
        out[(size_t)(c0 + y + 8 * j) * R + r0 + x] = t[x][y + 8 * j];
}

// ---------------------------------------------------------------------------
// tf32 mma.sync GEMM: C[M,N] = A[M,K] @ BT[N,K]^T (both k-contiguous).
// CTA tile 128x128, BK=32, 256 threads = 8 warps (2M x 4N), warp tile 64x32.
// ---------------------------------------------------------------------------
#define MM_BM 128
#define MM_BN 128
#define MM_BK 32
#define MM_STR 36
#define MM_THREADS 256
#define MM_TILE_U32 (MM_BM * MM_STR)
#define MM_SMEM_BYTES (4 * MM_TILE_U32 * 4)

__global__ __launch_bounds__(MM_THREADS)
void mma_gemm_kernel(int M, int N, int K,
                     const float* __restrict__ A,
                     const float* __restrict__ BT,
                     float* __restrict__ C)
{
    extern __shared__ uint32_t sm_u[];
    uint32_t* sA[2] = {sm_u, sm_u + 2 * MM_TILE_U32};
    uint32_t* sB[2] = {sm_u + MM_TILE_U32, sm_u + 3 * MM_TILE_U32};

    const int tid  = threadIdx.x;
    const int warp = tid >> 5;
    const int lane = tid & 31;
    const int g    = lane >> 2;
    const int tig  = lane & 3;

    const int wm = (warp >> 2) * 64;
    const int wn = (warp & 3) * 32;

    const int m0 = blockIdx.y * MM_BM;
    const int n0 = blockIdx.x * MM_BN;

    const int lrow = tid >> 3;
    const int lc4  = tid & 7;

    const float* Abase = A  + (size_t)(m0 + lrow) * K + lc4 * 4;
    const float* Bbase = BT + (size_t)(n0 + lrow) * K + lc4 * 4;

    float acc[4][4][4] = {};
    float4 ra[4], rb[4];

    const int NC = K / MM_BK;

    #pragma unroll
    for (int j = 0; j < 4; j++) {
        ra[j] = *(const float4*)(Abase + (size_t)(j * 32) * K);
        rb[j] = *(const float4*)(Bbase + (size_t)(j * 32) * K);
    }
    #pragma unroll
    for (int j = 0; j < 4; j++) {
        int off = (lrow + j * 32) * MM_STR + lc4 * 4;
        *(uint4*)(sA[0] + off) = make_uint4(f2tf32(ra[j].x), f2tf32(ra[j].y),
                                            f2tf32(ra[j].z), f2tf32(ra[j].w));
        *(uint4*)(sB[0] + off) = make_uint4(f2tf32(rb[j].x), f2tf32(rb[j].y),
                                            f2tf32(rb[j].z), f2tf32(rb[j].w));
    }
    __syncthreads();

    for (int c = 0; c < NC; c++) {
        const int buf = c & 1;

        if (c + 1 < NC) {
            const float* An = Abase + (size_t)(c + 1) * MM_BK;
            const float* Bn = Bbase + (size_t)(c + 1) * MM_BK;
            #pragma unroll
            for (int j = 0; j < 4; j++) {
                ra[j] = *(const float4*)(An + (size_t)(j * 32) * K);
                rb[j] = *(const float4*)(Bn + (size_t)(j * 32) * K);
            }
        }

        const uint32_t* As = sA[buf];
        const uint32_t* Bs = sB[buf];
        #pragma unroll
        for (int ks = 0; ks < 4; ks++) {
            const int k0 = ks * 8;
            uint32_t af[4][4], bf[4][2];
            #pragma unroll
            for (int mt = 0; mt < 4; mt++) {
                const int row = wm + mt * 16;
                af[mt][0] = As[(row + g) * MM_STR + k0 + tig];
                af[mt][1] = As[(row + g + 8) * MM_STR + k0 + tig];
                af[mt][2] = As[(row + g) * MM_STR + k0 + tig + 4];
                af[mt][3] = As[(row + g + 8) * MM_STR + k0 + tig + 4];
            }
            #pragma unroll
            for (int nt = 0; nt < 4; nt++) {
                const int col = wn + nt * 8 + g;
                bf[nt][0] = Bs[col * MM_STR + k0 + tig];
                bf[nt][1] = Bs[col * MM_STR + k0 + tig + 4];
            }
            #pragma unroll
            for (int mt = 0; mt < 4; mt++)
                #pragma unroll
                for (int nt = 0; nt < 4; nt++)
                    mma_tf32(acc[mt][nt], af[mt], bf[nt]);
        }

        if (c + 1 < NC) {
            __syncthreads();
            uint32_t* Ad = sA[buf ^ 1];
            uint32_t* Bd = sB[buf ^ 1];
            #pragma unroll
            for (int j = 0; j < 4; j++) {
                int off = (lrow + j * 32) * MM_STR + lc4 * 4;
                *(uint4*)(Ad + off) = make_uint4(f2tf32(ra[j].x), f2tf32(ra[j].y),
                                                 f2tf32(ra[j].z), f2tf32(ra[j].w));
                *(uint4*)(Bd + off) = make_uint4(f2tf32(rb[j].x), f2tf32(rb[j].y),
                                                 f2tf32(rb[j].z), f2tf32(rb[j].w));
            }
            __syncthreads();
        }
    }

    #pragma unroll
    for (int mt = 0; mt < 4; mt++) {
        const int row = m0 + wm + mt * 16 + g;
        #pragma unroll
        for (int nt = 0; nt < 4; nt++) {
            const int col = n0 + wn + nt * 8 + tig * 2;
            *(float2*)(C + (size_t)row * N + col) =
                make_float2(acc[mt][nt][0], acc[mt][nt][1]);
            *(float2*)(C + (size_t)(row + 8) * N + col) =
                make_float2(acc[mt][nt][2], acc[mt][nt][3]);
        }
    }
}

// ---------------------------------------------------------------------------
// RoPE: in-place on tensor rows [B*S] x (nheads*HDIM at given ld); freqs [S,32,2]
// ---------------------------------------------------------------------------
__global__ void rope_kernel(float* __restrict__ t,
                            const float* __restrict__ freqs,
                            int nheads, int ld, int total_pairs)
{
    int idx = blockIdx.x * blockDim.x + threadIdx.x;
    if (idx >= total_pairs) return;
    const int ppr = nheads * (HDIM / 2);
    int row = idx / ppr;
    int pr  = idx % ppr;
    int hh  = pr / (HDIM / 2);
    int i   = pr % (HDIM / 2);
    int s   = row % SEQ;
    float c  = freqs[s * HDIM + i * 2 + 0];
    float sn = freqs[s * HDIM + i * 2 + 1];
    float* p = t + (size_t)row * ld + hh * HDIM + i * 2;
    float xr = p[0], xi = p[1];
    p[0] = xr * c - xi * sn;
    p[1] = xr * sn + xi * c;
}

// ---------------------------------------------------------------------------
// FlashAttention-2 on tf32 mma.sync. CTA = 128 queries x one (b,h).
// 8 warps x 16 q rows each; K/V tiles of 64 keys; online softmax in registers.
// Smem strides: Q/K/P = 68 (bank 4g+tig bijective), V = 72 (bank 8tig+g bijective).
// ---------------------------------------------------------------------------
#define FA_QT 128
#define FA_KT 64
#define FA_THREADS 256
#define QS_STR 68
#define KS_STR 68
#define PS_STR 68
#define VS_STR 72

#define FA_QS 0
#define FA_KS (FA_QT * QS_STR)                    // 8704
#define FA_VS (FA_KS + FA_KT * KS_STR)            // 13056
#define FA_PS (FA_VS + FA_KT * VS_STR)            // 17664
#define FA_SMEM_FLOATS (FA_PS + FA_QT * PS_STR)   // 26368
#define FA_SMEM_BYTES (FA_SMEM_FLOATS * 4)        // 105472

__global__ __launch_bounds__(FA_THREADS)
void fa_kernel(const float* __restrict__ Q,
               const float* __restrict__ KV,
               float* __restrict__ O)
{
    extern __shared__ uint32_t smf[];
    uint32_t* Qs = smf + FA_QS;
    uint32_t* Ks = smf + FA_KS;
    uint32_t* Vs = smf + FA_VS;
    uint32_t* Ps = smf + FA_PS;

    const int tid  = threadIdx.x;
    const int warp = tid >> 5;
    const int lane = tid & 31;
    const int g    = lane >> 2;
    const int tig  = lane & 3;

    const int qt = blockIdx.x;
    const int h  = blockIdx.y;
    const int b  = blockIdx.z;
    const int kvh = h / GQA_REP;

    const int qrow0 = qt * FA_QT;
    const int wrow  = warp * 16;

    // load Q tile, scaled by 0.125*log2(e), tf32-rounded
    const float qscale = 0.18033688011112042f;
    {
        const float* Qg = Q + (size_t)(b * SEQ + qrow0) * (NHEADS * HDIM) + h * HDIM;
        #pragma unroll
        for (int it = 0; it < (FA_QT * 16) / FA_THREADS; it++) {
            int idx = tid + it * FA_THREADS;
            int r = idx >> 4, c4 = idx & 15;
            float4 v = *(const float4*)(Qg + (size_t)r * (NHEADS * HDIM) + c4 * 4);
            *(uint4*)(Qs + r * QS_STR + c4 * 4) =
                make_uint4(f2tf32(v.x * qscale), f2tf32(v.y * qscale),
                           f2tf32(v.z * qscale), f2tf32(v.w * qscale));
        }
    }

    float m0r = -1e30f, m1r = -1e30f;
    float l0r = 0.0f,  l1r = 0.0f;
    float o[8][4] = {};

    const int nkt = 2 * qt + 2;  // k tiles covering rows up to qrow0+127

    for (int kt = 0; kt < nkt; kt++) {
        // load K,V tiles (fused KV layout: K at col kvh*64, V at col 256+kvh*64)
        {
            const float* Kg = KV + (size_t)(b * SEQ + kt * FA_KT) * KVLD + kvh * HDIM;
            #pragma unroll
            for (int it = 0; it < (FA_KT * 16) / FA_THREADS; it++) {
                int idx = tid + it * FA_THREADS;
                int r = idx >> 4, c4 = idx & 15;
                const float* src = Kg + (size_t)r * KVLD + c4 * 4;
                float4 kv4 = *(const float4*)(src);
                float4 vv4 = *(const float4*)(src + NKVH * HDIM);
                *(uint4*)(Ks + r * KS_STR + c4 * 4) =
                    make_uint4(f2tf32(kv4.x), f2tf32(kv4.y), f2tf32(kv4.z), f2tf32(kv4.w));
                *(uint4*)(Vs + r * VS_STR + c4 * 4) =
                    make_uint4(f2tf32(vv4.x), f2tf32(vv4.y), f2tf32(vv4.z), f2tf32(vv4.w));
            }
        }
        __syncthreads();

        // warps whose rows are entirely left of this k tile skip compute
        const bool active = (kt * FA_KT <= qrow0 + wrow + 15);
        if (active) {
            // S = Q K^T  (log2-domain scores; scale folded into Q)
            float s[8][4] = {};
            #pragma unroll
            for (int ks = 0; ks < 8; ks++) {
                uint32_t a[4];
                a[0] = Qs[(wrow + g) * QS_STR + ks * 8 + tig];
                a[1] = Qs[(wrow + g + 8) * QS_STR + ks * 8 + tig];
                a[2] = Qs[(wrow + g) * QS_STR + ks * 8 + tig + 4];
                a[3] = Qs[(wrow + g + 8) * QS_STR + ks * 8 + tig + 4];
                #pragma unroll
                for (int nt = 0; nt < 8; nt++) {
                    uint32_t bf[2];
                    bf[0] = Ks[(nt * 8 + g) * KS_STR + ks * 8 + tig];
                    bf[1] = Ks[(nt * 8 + g) * KS_STR + ks * 8 + tig + 4];
                    mma_tf32(s[nt], a, bf);
                }
            }

            // causal mask (only diagonal-straddling tiles need it)
            if (kt * FA_KT + (FA_KT - 1) > qrow0 + wrow) {
                const int rg  = qrow0 + wrow + g;
                const int rg8 = rg + 8;
                #pragma unroll
                for (int nt = 0; nt < 8; nt++) {
                    const int c0 = kt * FA_KT + nt * 8 + 2 * tig;
                    const int c1 = c0 + 1;
                    if (c0 > rg)  s[nt][0] = -1e30f;
                    if (c1 > rg)  s[nt][1] = -1e30f;
                    if (c0 > rg8) s[nt][2] = -1e30f;
                    if (c1 > rg8) s[nt][3] = -1e30f;
                }
            }

            // online softmax (log2 domain)
            float mx0 = -1e30f, mx1 = -1e30f;
            #pragma unroll
            for (int nt = 0; nt < 8; nt++) {
                mx0 = fmaxf(mx0, fmaxf(s[nt][0], s[nt][1]));
                mx1 = fmaxf(mx1, fmaxf(s[nt][2], s[nt][3]));
            }
            mx0 = fmaxf(mx0, __shfl_xor_sync(0xffffffffu, mx0, 1));
            mx0 = fmaxf(mx0, __shfl_xor_sync(0xffffffffu, mx0, 2));
            mx1 = fmaxf(mx1, __shfl_xor_sync(0xffffffffu, mx1, 1));
            mx1 = fmaxf(mx1, __shfl_xor_sync(0xffffffffu, mx1, 2));

            const float mn0 = fmaxf(m0r, mx0);
            const float mn1 = fmaxf(m1r, mx1);
            const float al0 = fexp2(m0r - mn0);
            const float al1 = fexp2(m1r - mn1);
            m0r = mn0; m1r = mn1;

            float sum0 = 0.0f, sum1 = 0.0f;
            uint32_t* Pw  = Ps + (wrow + g) * PS_STR + 2 * tig;
            uint32_t* Pw8 = Ps + (wrow + g + 8) * PS_STR + 2 * tig;
            #pragma unroll
            for (int nt = 0; nt < 8; nt++) {
                float p0 = fexp2(s[nt][0] - mn0);
                float p1 = fexp2(s[nt][1] - mn0);
                float p2 = fexp2(s[nt][2] - mn1);
                float p3 = fexp2(s[nt][3] - mn1);
                sum0 += p0 + p1;
                sum1 += p2 + p3;
                *(uint2*)(Pw  + nt * 8) = make_uint2(f2tf32(p0), f2tf32(p1));
                *(uint2*)(Pw8 + nt * 8) = make_uint2(f2tf32(p2), f2tf32(p3));
            }
            sum0 += __shfl_xor_sync(0xffffffffu, sum0, 1);
            sum0 += __shfl_xor_sync(0xffffffffu, sum0, 2);
            sum1 += __shfl_xor_sync(0xffffffffu, sum1, 1);
            sum1 += __shfl_xor_sync(0xffffffffu, sum1, 2);
            l0r = l0r * al0 + sum0;
            l1r = l1r * al1 + sum1;

            #pragma unroll
            for (int nt = 0; nt < 8; nt++) {
                o[nt][0] *= al0; o[nt][1] *= al0;
                o[nt][2] *= al1; o[nt][3] *= al1;
            }
            __syncwarp();

            // O += P V   (P warp-private in smem; V shared)
            #pragma unroll
            for (int ks = 0; ks < 8; ks++) {
                uint32_t a[4];
                a[0] = Ps[(wrow + g) * PS_STR + ks * 8 + tig];
                a[1] = Ps[(wrow + g + 8) * PS_STR + ks * 8 + tig];
                a[2] = Ps[(wrow + g) * PS_STR + ks * 8 + tig + 4];
                a[3] = Ps[(wrow + g + 8) * PS_STR + ks * 8 + tig + 4];
                #pragma unroll
                for (int nt = 0; nt < 8; nt++) {
                    uint32_t bf[2];
                    bf[0] = Vs[(ks * 8 + tig) * VS_STR + nt * 8 + g];
                    bf[1] = Vs[(ks * 8 + tig + 4) * VS_STR + nt * 8 + g];
                    mma_tf32(o[nt], a, bf);
                }
            }
        }
        __syncthreads();
    }

    // epilogue
    const float il0 = 1.0f / l0r;
    const float il1 = 1.0f / l1r;
    float* Ob = O + (size_t)(b * SEQ + qrow0 + wrow) * (NHEADS * HDIM) + h * HDIM;
    #pragma unroll
    for (int nt = 0; nt < 8; nt++) {
        *(float2*)(Ob + (size_t)g * (NHEADS * HDIM) + nt * 8 + 2 * tig) =
            make_float2(o[nt][0] * il0, o[nt][1] * il0);
        *(float2*)(Ob + (size_t)(g + 8) * (NHEADS * HDIM) + nt * 8 + 2 * tig) =
            make_float2(o[nt][2] * il1, o[nt][3] * il1);
    }
}

// ---------------------------------------------------------------------------
// launch
// ---------------------------------------------------------------------------
extern "C" void kernel_launch(void* const* d_in, const int* in_sizes, int n_in,
                              void* d_out, int out_size)
{
    const float* x     = (const float*)d_in[0];
    const float* freqs = (const float*)d_in[1];
    // d_in[2] is the additive mask — exactly causal; handled in-kernel.
    const float* wq    = (const float*)d_in[3];
    const float* wk    = (const float*)d_in[4];
    const float* wv    = (const float*)d_in[5];
    const float* wo    = (const float*)d_in[6];
    float* out = (float*)d_out;

    static float *gq = nullptr, *gkv = nullptr, *gao = nullptr;
    static float *wqT = nullptr, *wkvT = nullptr, *woT = nullptr;
    if (!gq) {
        cudaGetSymbolAddress((void**)&gq,   g_q);
        cudaGetSymbolAddress((void**)&gkv,  g_kv);
        cudaGetSymbolAddress((void**)&gao,  g_ao);
        cudaGetSymbolAddress((void**)&wqT,  g_wqT);
        cudaGetSymbolAddress((void**)&wkvT, g_wkvT);
        cudaGetSymbolAddress((void**)&woT,  g_woT);
        cudaFuncSetAttribute(mma_gemm_kernel, cudaFuncAttributeMaxDynamicSharedMemorySize,
                             MM_SMEM_BYTES);
        cudaFuncSetAttribute(fa_kernel, cudaFuncAttributeMaxDynamicSharedMemorySize,
                             FA_SMEM_BYTES);
    }

    // transpose weights to k-major (N,K); wk,wv fused into one [512,2048]
    {
        dim3 blk(32, 8);
        transpose_kernel<<<dim3(DMODEL / 32, DMODEL / 32), blk>>>(wq, wqT, DMODEL, DMODEL);
        transpose_kernel<<<dim3((NKVH * HDIM) / 32, DMODEL / 32), blk>>>(
            wk, wkvT, DMODEL, NKVH * HDIM);
        transpose_kernel<<<dim3((NKVH * HDIM) / 32, DMODEL / 32), blk>>>(
            wv, wkvT + (size_t)(NKVH * HDIM) * DMODEL, DMODEL, NKVH * HDIM);
        transpose_kernel<<<dim3(DMODEL / 32, DMODEL / 32), blk>>>(wo, woT, DMODEL, DMODEL);
    }

    // projections (tf32 mma): Q, then fused [K|V]
    mma_gemm_kernel<<<dim3(DMODEL / MM_BN, MROWS / MM_BM), MM_THREADS, MM_SMEM_BYTES>>>(
        MROWS, DMODEL, DMODEL, x, wqT, gq);
    mma_gemm_kernel<<<dim3(KVLD / MM_BN, MROWS / MM_BM), MM_THREADS, MM_SMEM_BYTES>>>(
        MROWS, KVLD, DMODEL, x, wkvT, gkv);

    // RoPE on Q and K (K lives in fused KV buffer, cols 0..255)
    {
        int pq = MROWS * NHEADS * (HDIM / 2);
        int pk = MROWS * NKVH * (HDIM / 2);
        rope_kernel<<<(pq + 255) / 256, 256>>>(gq, freqs, NHEADS, NHEADS * HDIM, pq);
        rope_kernel<<<(pk + 255) / 256, 256>>>(gkv, freqs, NKVH, KVLD, pk);
    }

    // attention (tf32 mma flash)
    fa_kernel<<<dim3(SEQ / FA_QT, NHEADS, BATCH), FA_THREADS, FA_SMEM_BYTES>>>(gq, gkv, gao);

    // output projection
    mma_gemm_kernel<<<dim3(DMODEL / MM_BN, MROWS / MM_BM), MM_THREADS, MM_SMEM_BYTES>>>(
        MROWS, DMODEL, DMODEL, gao, woT, out);
}

// round 5
// speedup vs baseline: 4.2526x; 1.1382x over previous
#include <cuda_runtime.h>
#include <cuda_bf16.h>
#include <math.h>
#include <stdint.h>

// Problem constants
#define BATCH 2
#define SEQ   2048
#define DMODEL 2048
#define NHEADS 32
#define NKVH   4
#define HDIM   64
#define GQA_REP (NHEADS / NKVH)   // 8
#define MROWS (BATCH * SEQ)       // 4096
#define KVLD  (2 * NKVH * HDIM)   // 512: fused [K|V] row stride

// Scratch (device globals; no runtime allocation allowed)
__device__ float g_x[MROWS * DMODEL];           // tf32-rounded x
__device__ float g_q[MROWS * NHEADS * HDIM];    // [4096, 2048]
__device__ float g_kv[MROWS * KVLD];            // [4096, 512] (K 0..255, V 256..511)
__device__ float g_ao[MROWS * NHEADS * HDIM];   // [4096, 2048]
__device__ float g_wqT[DMODEL * DMODEL];        // (N,K) k-major, tf32-rounded
__device__ float g_wkvT[KVLD * DMODEL];
__device__ float g_woT[DMODEL * DMODEL];

// ---------------------------------------------------------------------------
// helpers
// ---------------------------------------------------------------------------
__device__ __forceinline__ uint32_t smem_u32(const void* p) {
    uint32_t a;
    asm("{ .reg .u64 t; cvta.to.shared.u64 t, %1; cvt.u32.u64 %0, t; }"
        : "=r"(a) : "l"(p));
    return a;
}
__device__ __forceinline__ uint32_t f2tf32(float f) {
    uint32_t u;
    asm("cvt.rna.tf32.f32 %0, %1;" : "=r"(u) : "f"(f));
    return u;
}
__device__ __forceinline__ float fexp2(float x) {
    float y;
    asm("ex2.approx.ftz.f32 %0, %1;" : "=f"(y) : "f"(x));
    return y;
}
__device__ __forceinline__ void mma_tf32(float* d, const uint32_t* a, const uint32_t* b) {
    asm volatile(
        "mma.sync.aligned.m16n8k8.row.col.f32.tf32.tf32.f32 "
        "{%0,%1,%2,%3}, {%4,%5,%6,%7}, {%8,%9}, {%0,%1,%2,%3};"
        : "+f"(d[0]), "+f"(d[1]), "+f"(d[2]), "+f"(d[3])
        : "r"(a[0]), "r"(a[1]), "r"(a[2]), "r"(a[3]), "r"(b[0]), "r"(b[1]));
}
__device__ __forceinline__ void cp16(uint32_t saddr, const void* g) {
    asm volatile("cp.async.cg.shared.global [%0], [%1], 16;" :: "r"(saddr), "l"(g));
}
#define CP_COMMIT() asm volatile("cp.async.commit_group;" ::: "memory")
#define CP_WAIT1()  asm volatile("cp.async.wait_group 1;" ::: "memory")

// ---------------------------------------------------------------------------
// x -> tf32-rounded copy
// ---------------------------------------------------------------------------
__global__ void round_tf32_kernel(const float* __restrict__ in, float* __restrict__ out,
                                  int n4)
{
    int i = blockIdx.x * blockDim.x + threadIdx.x;
    if (i >= n4) return;
    float4 v = ((const float4*)in)[i];
    uint4 u = make_uint4(f2tf32(v.x), f2tf32(v.y), f2tf32(v.z), f2tf32(v.w));
    ((uint4*)out)[i] = u;
}

// ---------------------------------------------------------------------------
// Weight transpose (writes tf32-rounded): in [R,C] -> out [C,R]
// ---------------------------------------------------------------------------
__global__ void transpose_kernel(const float* __restrict__ in, float* __restrict__ out,
                                 int R, int C)
{
    __shared__ float t[32][33];
    int c0 = blockIdx.x * 32, r0 = blockIdx.y * 32;
    int x = threadIdx.x, y = threadIdx.y;  // 32 x 8
    #pragma unroll
    for (int j = 0; j < 4; j++)
        t[y + 8 * j][x] = in[(size_t)(r0 + y + 8 * j) * C + c0 + x];
    __syncthreads();
    #pragma unroll
    for (int j = 0; j < 4; j++)
        out[(size_t)(c0 + y + 8 * j) * R + r0 + x] =
            __uint_as_float(f2tf32(t[x][y + 8 * j]));
}

// ---------------------------------------------------------------------------
// tf32 mma.sync GEMM, cp.async 3-stage pipeline.
// C[M,N] = A[M,K] @ BT[N,K]^T; A,BT hold pre-rounded tf32 bits.
// CTA 128x128, BK=32, 256 threads = 8 warps (2Mx4N), warp tile 64x32.
// ---------------------------------------------------------------------------
#define MM_BM 128
#define MM_BN 128
#define MM_BK 32
#define MM_STR 36
#define MM_THREADS 256
#define MM_TILE_U32 (MM_BM * MM_STR)            // 4608
#define MM_STAGE_U32 (2 * MM_TILE_U32)          // 9216
#define MM_STAGES 3
#define MM_SMEM_BYTES (MM_STAGES * MM_STAGE_U32 * 4)  // 110592

__global__ __launch_bounds__(MM_THREADS)
void mma_gemm_kernel(int M, int N, int K,
                     const float* __restrict__ A,
                     const float* __restrict__ BT,
                     float* __restrict__ C,
                     int round_out)
{
    extern __shared__ uint32_t sm_u[];
    const uint32_t sbase = smem_u32(sm_u);

    const int tid  = threadIdx.x;
    const int warp = tid >> 5;
    const int lane = tid & 31;
    const int g    = lane >> 2;
    const int tig  = lane & 3;

    const int wm = (warp >> 2) * 64;
    const int wn = (warp & 3) * 32;

    const int m0 = blockIdx.y * MM_BM;
    const int n0 = blockIdx.x * MM_BN;

    const int lrow = tid >> 3;   // 0..31
    const int lc4  = tid & 7;    // 0..7

    const float* Abase = A  + (size_t)(m0 + lrow) * K + lc4 * 4;
    const float* Bbase = BT + (size_t)(n0 + lrow) * K + lc4 * 4;

    const uint32_t sA_thr = (uint32_t)(lrow * MM_STR + lc4 * 4) * 4;

    auto issue = [&](int c, int slot) {
        const float* Ac = Abase + (size_t)c * MM_BK;
        const float* Bc = Bbase + (size_t)c * MM_BK;
        uint32_t abase_s = sbase + (uint32_t)slot * MM_STAGE_U32 * 4 + sA_thr;
        uint32_t bbase_s = abase_s + MM_TILE_U32 * 4;
        #pragma unroll
        for (int j = 0; j < 4; j++) {
            cp16(abase_s + j * 32 * MM_STR * 4, Ac + (size_t)(j * 32) * K);
            cp16(bbase_s + j * 32 * MM_STR * 4, Bc + (size_t)(j * 32) * K);
        }
    };

    const int NC = K / MM_BK;
    issue(0, 0); CP_COMMIT();
    issue(1, 1); CP_COMMIT();

    float acc[4][4][4] = {};

    for (int c = 0; c < NC; c++) {
        CP_WAIT1();          // group c complete
        __syncthreads();
        if (c + 2 < NC) issue(c + 2, (c + 2) % MM_STAGES);
        CP_COMMIT();         // always commit: keeps group numbering uniform

        const uint32_t* As = sm_u + (c % MM_STAGES) * MM_STAGE_U32;
        const uint32_t* Bs = As + MM_TILE_U32;
        #pragma unroll
        for (int ks = 0; ks < 4; ks++) {
            const int k0 = ks * 8;
            uint32_t af[4][4], bf[4][2];
            #pragma unroll
            for (int mt = 0; mt < 4; mt++) {
                const int row = wm + mt * 16;
                af[mt][0] = As[(row + g) * MM_STR + k0 + tig];
                af[mt][1] = As[(row + g + 8) * MM_STR + k0 + tig];
                af[mt][2] = As[(row + g) * MM_STR + k0 + tig + 4];
                af[mt][3] = As[(row + g + 8) * MM_STR + k0 + tig + 4];
            }
            #pragma unroll
            for (int nt = 0; nt < 4; nt++) {
                const int col = wn + nt * 8 + g;
                bf[nt][0] = Bs[col * MM_STR + k0 + tig];
                bf[nt][1] = Bs[col * MM_STR + k0 + tig + 4];
            }
            #pragma unroll
            for (int mt = 0; mt < 4; mt++)
                #pragma unroll
                for (int nt = 0; nt < 4; nt++)
                    mma_tf32(acc[mt][nt], af[mt], bf[nt]);
        }
    }

    #pragma unroll
    for (int mt = 0; mt < 4; mt++) {
        const int row = m0 + wm + mt * 16 + g;
        #pragma unroll
        for (int nt = 0; nt < 4; nt++) {
            const int col = n0 + wn + nt * 8 + tig * 2;
            if (round_out) {
                *(float2*)(C + (size_t)row * N + col) =
                    make_float2(__uint_as_float(f2tf32(acc[mt][nt][0])),
                                __uint_as_float(f2tf32(acc[mt][nt][1])));
                *(float2*)(C + (size_t)(row + 8) * N + col) =
                    make_float2(__uint_as_float(f2tf32(acc[mt][nt][2])),
                                __uint_as_float(f2tf32(acc[mt][nt][3])));
            } else {
                *(float2*)(C + (size_t)row * N + col) =
                    make_float2(acc[mt][nt][0], acc[mt][nt][1]);
                *(float2*)(C + (size_t)(row + 8) * N + col) =
                    make_float2(acc[mt][nt][2], acc[mt][nt][3]);
            }
        }
    }
}

// ---------------------------------------------------------------------------
// RoPE: rotate pairs, multiply by scale, write tf32-rounded bits.
// ---------------------------------------------------------------------------
__global__ void rope_kernel(float* __restrict__ t,
                            const float* __restrict__ freqs,
                            int nheads, int ld, int total_pairs, float scale)
{
    int idx = blockIdx.x * blockDim.x + threadIdx.x;
    if (idx >= total_pairs) return;
    const int ppr = nheads * (HDIM / 2);
    int row = idx / ppr;
    int pr  = idx % ppr;
    int hh  = pr / (HDIM / 2);
    int i   = pr % (HDIM / 2);
    int s   = row % SEQ;
    float c  = freqs[s * HDIM + i * 2 + 0];
    float sn = freqs[s * HDIM + i * 2 + 1];
    float* p = t + (size_t)row * ld + hh * HDIM + i * 2;
    float xr = p[0], xi = p[1];
    p[0] = __uint_as_float(f2tf32((xr * c - xi * sn) * scale));
    p[1] = __uint_as_float(f2tf32((xr * sn + xi * c) * scale));
}

// ---------------------------------------------------------------------------
// FlashAttention-2 on tf32 mma.sync, cp.async double-buffered K/V.
// CTA = 128 queries x one (b,h); 8 warps x 16 rows; K/V tiles of 64.
// Q fragments hoisted to registers; Q smem region reused as K double-buffer.
// Inputs Q (pre-scaled by 0.125*log2e) / K / V hold pre-rounded tf32 bits.
// ---------------------------------------------------------------------------
#define FA_QT 128
#define FA_KT 64
#define FA_THREADS 256
#define QS_STR 68
#define KS_STR 68
#define PS_STR 68
#define VS_STR 72

#define FA_QK 0                                   // Q tile, later K double-buf (8704 u32)
#define FA_VOFF 8704                              // V double-buf (2*64*72 = 9216)
#define FA_POFF (FA_VOFF + 2 * FA_KT * VS_STR)    // 17920: P (128*68 = 8704)
#define FA_SMEM_U32 (FA_POFF + FA_QT * PS_STR)    // 26624
#define FA_SMEM_BYTES (FA_SMEM_U32 * 4)           // 106496

__global__ __launch_bounds__(FA_THREADS, 2)
void fa_kernel(const float* __restrict__ Q,
               const float* __restrict__ KV,
               float* __restrict__ O)
{
    extern __shared__ uint32_t smf[];
    uint32_t* Qs = smf + FA_QK;
    uint32_t* Vs = smf + FA_VOFF;
    uint32_t* Ps = smf + FA_POFF;
    const uint32_t sbase = smem_u32(smf);

    const int tid  = threadIdx.x;
    const int warp = tid >> 5;
    const int lane = tid & 31;
    const int g    = lane >> 2;
    const int tig  = lane & 3;

    const int qt = (gridDim.x - 1) - blockIdx.x;   // heavy tiles first
    const int h  = blockIdx.y;
    const int b  = blockIdx.z;
    const int kvh = h / GQA_REP;

    const int qrow0 = qt * FA_QT;
    const int wrow  = warp * 16;

    // --- load Q tile (raw bit copy; pre-scaled + pre-rounded by rope)
    {
        const float* Qg = Q + (size_t)(b * SEQ + qrow0) * (NHEADS * HDIM) + h * HDIM;
        #pragma unroll
        for (int it = 0; it < 8; it++) {
            int idx = tid + it * FA_THREADS;
            int r = idx >> 4, c4 = idx & 15;
            *(uint4*)(Qs + r * QS_STR + c4 * 4) =
                *(const uint4*)(Qg + (size_t)r * (NHEADS * HDIM) + c4 * 4);
        }
    }
    __syncthreads();

    // --- hoist Q fragments into registers
    uint32_t qf[8][4];
    #pragma unroll
    for (int ks = 0; ks < 8; ks++) {
        qf[ks][0] = Qs[(wrow + g) * QS_STR + ks * 8 + tig];
        qf[ks][1] = Qs[(wrow + g + 8) * QS_STR + ks * 8 + tig];
        qf[ks][2] = Qs[(wrow + g) * QS_STR + ks * 8 + tig + 4];
        qf[ks][3] = Qs[(wrow + g + 8) * QS_STR + ks * 8 + tig + 4];
    }
    __syncthreads();   // Q region now free -> K double buffer

    const float* KVb = KV + (size_t)(b * SEQ) * KVLD + kvh * HDIM;

    auto issue = [&](int kt_, int slot) {
        const float* Kg = KVb + (size_t)(kt_ * FA_KT) * KVLD;
        #pragma unroll
        for (int it = 0; it < 4; it++) {
            int idx = tid + it * FA_THREADS;
            int r = idx >> 4, c4 = idx & 15;
            const float* src = Kg + (size_t)r * KVLD + c4 * 4;
            uint32_t kaddr = sbase + 4u * (slot * (FA_KT * KS_STR) + r * KS_STR + c4 * 4);
            uint32_t vaddr = sbase + 4u * (FA_VOFF + slot * (FA_KT * VS_STR) + r * VS_STR + c4 * 4);
            cp16(kaddr, src);
            cp16(vaddr, src + NKVH * HDIM);
        }
    };

    const int nkt = 2 * qt + 2;   // >= 2 always
    issue(0, 0); CP_COMMIT();
    issue(1, 1); CP_COMMIT();

    float m0r = -1e30f, m1r = -1e30f;
    float l0r = 0.0f,  l1r = 0.0f;
    float o[8][4] = {};

    for (int kt = 0; kt < nkt; kt++) {
        CP_WAIT1();            // group kt complete
        __syncthreads();

        const uint32_t* Kb = Qs + (kt & 1) * (FA_KT * KS_STR);
        const uint32_t* Vb = Vs + (kt & 1) * (FA_KT * VS_STR);

        const bool active = (kt * FA_KT <= qrow0 + wrow + 15);
        if (active) {
            // S = Q K^T (log2-domain; scale folded into Q)
            float s[8][4] = {};
            #pragma unroll
            for (int ks = 0; ks < 8; ks++) {
                #pragma unroll
                for (int nt = 0; nt < 8; nt++) {
                    uint32_t bf[2];
                    bf[0] = Kb[(nt * 8 + g) * KS_STR + ks * 8 + tig];
                    bf[1] = Kb[(nt * 8 + g) * KS_STR + ks * 8 + tig + 4];
                    mma_tf32(s[nt], qf[ks], bf);
                }
            }

            // causal mask on diagonal-straddling tiles
            if (kt * FA_KT + (FA_KT - 1) > qrow0 + wrow) {
                const int rg  = qrow0 + wrow + g;
                const int rg8 = rg + 8;
                #pragma unroll
                for (int nt = 0; nt < 8; nt++) {
                    const int c0 = kt * FA_KT + nt * 8 + 2 * tig;
                    const int c1 = c0 + 1;
                    if (c0 > rg)  s[nt][0] = -1e30f;
                    if (c1 > rg)  s[nt][1] = -1e30f;
                    if (c0 > rg8) s[nt][2] = -1e30f;
                    if (c1 > rg8) s[nt][3] = -1e30f;
                }
            }

            // online softmax (log2 domain)
            float mx0 = -1e30f, mx1 = -1e30f;
            #pragma unroll
            for (int nt = 0; nt < 8; nt++) {
                mx0 = fmaxf(mx0, fmaxf(s[nt][0], s[nt][1]));
                mx1 = fmaxf(mx1, fmaxf(s[nt][2], s[nt][3]));
            }
            mx0 = fmaxf(mx0, __shfl_xor_sync(0xffffffffu, mx0, 1));
            mx0 = fmaxf(mx0, __shfl_xor_sync(0xffffffffu, mx0, 2));
            mx1 = fmaxf(mx1, __shfl_xor_sync(0xffffffffu, mx1, 1));
            mx1 = fmaxf(mx1, __shfl_xor_sync(0xffffffffu, mx1, 2));

            const float mn0 = fmaxf(m0r, mx0);
            const float mn1 = fmaxf(m1r, mx1);
            const float al0 = fexp2(m0r - mn0);
            const float al1 = fexp2(m1r - mn1);
            m0r = mn0; m1r = mn1;

            float sum0 = 0.0f, sum1 = 0.0f;
            uint32_t* Pw  = Ps + (wrow + g) * PS_STR + 2 * tig;
            uint32_t* Pw8 = Ps + (wrow + g + 8) * PS_STR + 2 * tig;
            #pragma unroll
            for (int nt = 0; nt < 8; nt++) {
                float p0 = fexp2(s[nt][0] - mn0);
                float p1 = fexp2(s[nt][1] - mn0);
                float p2 = fexp2(s[nt][2] - mn1);
                float p3 = fexp2(s[nt][3] - mn1);
                sum0 += p0 + p1;
                sum1 += p2 + p3;
                *(uint2*)(Pw  + nt * 8) = make_uint2(f2tf32(p0), f2tf32(p1));
                *(uint2*)(Pw8 + nt * 8) = make_uint2(f2tf32(p2), f2tf32(p3));
            }
            sum0 += __shfl_xor_sync(0xffffffffu, sum0, 1);
            sum0 += __shfl_xor_sync(0xffffffffu, sum0, 2);
            sum1 += __shfl_xor_sync(0xffffffffu, sum1, 1);
            sum1 += __shfl_xor_sync(0xffffffffu, sum1, 2);
            l0r = l0r * al0 + sum0;
            l1r = l1r * al1 + sum1;

            #pragma unroll
            for (int nt = 0; nt < 8; nt++) {
                o[nt][0] *= al0; o[nt][1] *= al0;
                o[nt][2] *= al1; o[nt][3] *= al1;
            }
            __syncwarp();

            // O += P V (P warp-private in smem)
            #pragma unroll
            for (int ks = 0; ks < 8; ks++) {
                uint32_t a[4];
                a[0] = Ps[(wrow + g) * PS_STR + ks * 8 + tig];
                a[1] = Ps[(wrow + g + 8) * PS_STR + ks * 8 + tig];
                a[2] = Ps[(wrow + g) * PS_STR + ks * 8 + tig + 4];
                a[3] = Ps[(wrow + g + 8) * PS_STR + ks * 8 + tig + 4];
                #pragma unroll
                for (int nt = 0; nt < 8; nt++) {
                    uint32_t bf[2];
                    bf[0] = Vb[(ks * 8 + tig) * VS_STR + nt * 8 + g];
                    bf[1] = Vb[(ks * 8 + tig + 4) * VS_STR + nt * 8 + g];
                    mma_tf32(o[nt], a, bf);
                }
            }
        }
        __syncthreads();
        if (kt + 2 < nkt) issue(kt + 2, kt & 1);
        CP_COMMIT();   // always commit: uniform group numbering
    }

    // epilogue: write tf32-rounded (feeds wo GEMM via cp.async)
    const float il0 = 1.0f / l0r;
    const float il1 = 1.0f / l1r;
    float* Ob = O + (size_t)(b * SEQ + qrow0 + wrow) * (NHEADS * HDIM) + h * HDIM;
    #pragma unroll
    for (int nt = 0; nt < 8; nt++) {
        *(float2*)(Ob + (size_t)g * (NHEADS * HDIM) + nt * 8 + 2 * tig) =
            make_float2(__uint_as_float(f2tf32(o[nt][0] * il0)),
                        __uint_as_float(f2tf32(o[nt][1] * il0)));
        *(float2*)(Ob + (size_t)(g + 8) * (NHEADS * HDIM) + nt * 8 + 2 * tig) =
            make_float2(__uint_as_float(f2tf32(o[nt][2] * il1)),
                        __uint_as_float(f2tf32(o[nt][3] * il1)));
    }
}

// ---------------------------------------------------------------------------
// launch
// ---------------------------------------------------------------------------
extern "C" void kernel_launch(void* const* d_in, const int* in_sizes, int n_in,
                              void* d_out, int out_size)
{
    const float* x     = (const float*)d_in[0];
    const float* freqs = (const float*)d_in[1];
    // d_in[2] is the additive mask — exactly causal; handled in-kernel.
    const float* wq    = (const float*)d_in[3];
    const float* wk    = (const float*)d_in[4];
    const float* wv    = (const float*)d_in[5];
    const float* wo    = (const float*)d_in[6];
    float* out = (float*)d_out;

    static float *gx = nullptr, *gq = nullptr, *gkv = nullptr, *gao = nullptr;
    static float *wqT = nullptr, *wkvT = nullptr, *woT = nullptr;
    if (!gx) {
        cudaGetSymbolAddress((void**)&gx,   g_x);
        cudaGetSymbolAddress((void**)&gq,   g_q);
        cudaGetSymbolAddress((void**)&gkv,  g_kv);
        cudaGetSymbolAddress((void**)&gao,  g_ao);
        cudaGetSymbolAddress((void**)&wqT,  g_wqT);
        cudaGetSymbolAddress((void**)&wkvT, g_wkvT);
        cudaGetSymbolAddress((void**)&woT,  g_woT);
        cudaFuncSetAttribute(mma_gemm_kernel, cudaFuncAttributeMaxDynamicSharedMemorySize,
                             MM_SMEM_BYTES);
        cudaFuncSetAttribute(fa_kernel, cudaFuncAttributeMaxDynamicSharedMemorySize,
                             FA_SMEM_BYTES);
    }

    // pre-round x; transpose weights (rounded) to k-major
    round_tf32_kernel<<<(MROWS * DMODEL / 4 + 255) / 256, 256>>>(x, gx, MROWS * DMODEL / 4);
    {
        dim3 blk(32, 8);
        transpose_kernel<<<dim3(DMODEL / 32, DMODEL / 32), blk>>>(wq, wqT, DMODEL, DMODEL);
        transpose_kernel<<<dim3((NKVH * HDIM) / 32, DMODEL / 32), blk>>>(
            wk, wkvT, DMODEL, NKVH * HDIM);
        transpose_kernel<<<dim3((NKVH * HDIM) / 32, DMODEL / 32), blk>>>(
            wv, wkvT + (size_t)(NKVH * HDIM) * DMODEL, DMODEL, NKVH * HDIM);
        transpose_kernel<<<dim3(DMODEL / 32, DMODEL / 32), blk>>>(wo, woT, DMODEL, DMODEL);
    }

    // projections: Q (rope rounds later), fused [K|V] (rounded epilogue)
    mma_gemm_kernel<<<dim3(DMODEL / MM_BN, MROWS / MM_BM), MM_THREADS, MM_SMEM_BYTES>>>(
        MROWS, DMODEL, DMODEL, gx, wqT, gq, 0);
    mma_gemm_kernel<<<dim3(KVLD / MM_BN, MROWS / MM_BM), MM_THREADS, MM_SMEM_BYTES>>>(
        MROWS, KVLD, DMODEL, gx, wkvT, gkv, 1);

    // RoPE: Q gets 0.125*log2(e) folded in + rounded; K rounded
    {
        const float qscale = 0.18033688011112042f;
        int pq = MROWS * NHEADS * (HDIM / 2);
        int pk = MROWS * NKVH * (HDIM / 2);
        rope_kernel<<<(pq + 255) / 256, 256>>>(gq, freqs, NHEADS, NHEADS * HDIM, pq, qscale);
        rope_kernel<<<(pk + 255) / 256, 256>>>(gkv, freqs, NKVH, KVLD, pk, 1.0f);
    }

    // attention
    fa_kernel<<<dim3(SEQ / FA_QT, NHEADS, BATCH), FA_THREADS, FA_SMEM_BYTES>>>(gq, gkv, gao);

    // output projection (exact fp32 epilogue)
    mma_gemm_kernel<<<dim3(DMODEL / MM_BN, MROWS / MM_BM), MM_THREADS, MM_SMEM_BYTES>>>(
        MROWS, DMODEL, DMODEL, gao, woT, out, 0);
}

// round 6
// speedup vs baseline: 8.1085x; 1.9067x over previous
#include <cuda_runtime.h>
#include <cuda_fp16.h>
#include <math.h>
#include <stdint.h>

// Problem constants
#define BATCH 2
#define SEQ   2048
#define DMODEL 2048
#define NHEADS 32
#define NKVH   4
#define HDIM   64
#define GQA_REP (NHEADS / NKVH)   // 8
#define MROWS (BATCH * SEQ)       // 4096
#define KVLD  (2 * NKVH * HDIM)   // 512: fused [K|V] gemm output stride

// Scratch (device globals; no runtime allocation allowed)
__device__ __half g_xh[MROWS * DMODEL];
__device__ float  g_q[MROWS * NHEADS * HDIM];    // fp32 q (pre-rope)
__device__ __half g_qh[MROWS * NHEADS * HDIM];   // rope'd, scaled, half
__device__ float  g_kv[MROWS * KVLD];            // fp32 [K|V]
__device__ __half g_kh[MROWS * NKVH * HDIM];     // rope'd K, half [4096,256]
__device__ __half g_vt[NKVH * HDIM * MROWS];     // V^T half [256, 4096]
__device__ __half g_aoh[MROWS * NHEADS * HDIM];  // attention out, half
__device__ __half g_wqTh[DMODEL * DMODEL];       // (N,K) k-major half
__device__ __half g_wkvTh[KVLD * DMODEL];
__device__ __half g_woTh[DMODEL * DMODEL];

// ---------------------------------------------------------------------------
// helpers
// ---------------------------------------------------------------------------
__device__ __forceinline__ uint32_t smem_u32(const void* p) {
    uint32_t a;
    asm("{ .reg .u64 t; cvta.to.shared.u64 t, %1; cvt.u32.u64 %0, t; }"
        : "=r"(a) : "l"(p));
    return a;
}
__device__ __forceinline__ float fexp2(float x) {
    float y;
    asm("ex2.approx.ftz.f32 %0, %1;" : "=f"(y) : "f"(x));
    return y;
}
__device__ __forceinline__ uint32_t packh2(float lo, float hi) {
    __half2 h = __floats2half2_rn(lo, hi);
    return *reinterpret_cast<uint32_t*>(&h);
}
__device__ __forceinline__ void mma_f16(float* d, const uint32_t* a, const uint32_t* b) {
    asm volatile(
        "mma.sync.aligned.m16n8k16.row.col.f32.f16.f16.f32 "
        "{%0,%1,%2,%3}, {%4,%5,%6,%7}, {%8,%9}, {%0,%1,%2,%3};"
        : "+f"(d[0]), "+f"(d[1]), "+f"(d[2]), "+f"(d[3])
        : "r"(a[0]), "r"(a[1]), "r"(a[2]), "r"(a[3]), "r"(b[0]), "r"(b[1]));
}
__device__ __forceinline__ void cp16(uint32_t saddr, const void* g) {
    asm volatile("cp.async.cg.shared.global [%0], [%1], 16;" :: "r"(saddr), "l"(g));
}
#define CP_COMMIT() asm volatile("cp.async.commit_group;" ::: "memory")
#define CP_WAIT1()  asm volatile("cp.async.wait_group 1;" ::: "memory")

// ---------------------------------------------------------------------------
// x (fp32) -> half
// ---------------------------------------------------------------------------
__global__ void cvt_half_kernel(const float* __restrict__ in, __half* __restrict__ out,
                                int n8)
{
    int i = blockIdx.x * blockDim.x + threadIdx.x;
    if (i >= n8) return;
    float4 a = ((const float4*)in)[2 * i];
    float4 b = ((const float4*)in)[2 * i + 1];
    uint4 u = make_uint4(packh2(a.x, a.y), packh2(a.z, a.w),
                         packh2(b.x, b.y), packh2(b.z, b.w));
    ((uint4*)out)[i] = u;
}

// ---------------------------------------------------------------------------
// Weight transpose to half: in [R,C] fp32 -> out [C,R] half
// ---------------------------------------------------------------------------
__global__ void transpose_w_kernel(const float* __restrict__ in, __half* __restrict__ out,
                                   int R, int C)
{
    __shared__ float t[32][33];
    int c0 = blockIdx.x * 32, r0 = blockIdx.y * 32;
    int x = threadIdx.x, y = threadIdx.y;  // 32 x 8
    #pragma unroll
    for (int j = 0; j < 4; j++)
        t[y + 8 * j][x] = in[(size_t)(r0 + y + 8 * j) * C + c0 + x];
    __syncthreads();
    #pragma unroll
    for (int j = 0; j < 4; j++)
        out[(size_t)(c0 + y + 8 * j) * R + r0 + x] = __float2half_rn(t[x][y + 8 * j]);
}

// V transpose: g_kv [4096, 512] (V = cols 256..511) -> vt half [256, 4096]
__global__ void transpose_v_kernel(const float* __restrict__ kv, __half* __restrict__ vt)
{
    __shared__ float t[32][33];
    int c0 = blockIdx.x * 32;   // d (0..255)
    int r0 = blockIdx.y * 32;   // seq row
    int x = threadIdx.x, y = threadIdx.y;
    #pragma unroll
    for (int j = 0; j < 4; j++)
        t[y + 8 * j][x] = kv[(size_t)(r0 + y + 8 * j) * KVLD + 256 + c0 + x];
    __syncthreads();
    #pragma unroll
    for (int j = 0; j < 4; j++)
        vt[(size_t)(c0 + y + 8 * j) * MROWS + r0 + x] = __float2half_rn(t[x][y + 8 * j]);
}

// ---------------------------------------------------------------------------
// fp16 mma.sync GEMM: C[M,N](fp32) = A[M,K] @ BT[N,K]^T, A/BT half.
// CTA 128x128, BK=64 halfs, 256 threads = 8 warps (2Mx4N), warp tile 64x32.
// Smem rows: 32 words (+4 pad = stride 36) -> conflict-free (bank 4g+tig).
// 3-stage cp.async pipeline.
// ---------------------------------------------------------------------------
#define MM_BM 128
#define MM_BN 128
#define MM_BKH 64
#define MM_STRW 36
#define MM_THREADS 256
#define MM_TILE_W (MM_BM * MM_STRW)            // 4608 words
#define MM_STAGE_W (2 * MM_TILE_W)             // 9216
#define MM_STAGES 3
#define MM_SMEM_BYTES (MM_STAGES * MM_STAGE_W * 4)   // 110592

__global__ __launch_bounds__(MM_THREADS)
void mma_gemm_f16_kernel(int M, int N, int K,
                         const __half* __restrict__ A,
                         const __half* __restrict__ BT,
                         float* __restrict__ C)
{
    extern __shared__ uint32_t sm_u[];
    const uint32_t sbase = smem_u32(sm_u);

    const int tid  = threadIdx.x;
    const int warp = tid >> 5;
    const int lane = tid & 31;
    const int g    = lane >> 2;
    const int tig  = lane & 3;

    const int wm = (warp >> 2) * 64;
    const int wn = (warp & 3) * 32;

    const int m0 = blockIdx.y * MM_BM;
    const int n0 = blockIdx.x * MM_BN;

    // loader: 1024 cp16 per operand per chunk; per thread j<4: i = tid + 256j
    const int lr = tid >> 3;        // base row 0..31 (row = lr + 32*(j>>... ) no: i>>3)
    const int lc = tid & 7;         // 16B column 0..7

    auto issue = [&](int c, int slot) {
        const uint32_t sa = sbase + 4u * (slot * MM_STAGE_W);
        #pragma unroll
        for (int j = 0; j < 4; j++) {
            int r = lr + j * 32;
            cp16(sa + 4u * (r * MM_STRW + lc * 4),
                 A + (size_t)(m0 + r) * K + c * MM_BKH + lc * 8);
            cp16(sa + 4u * (MM_TILE_W + r * MM_STRW + lc * 4),
                 BT + (size_t)(n0 + r) * K + c * MM_BKH + lc * 8);
        }
    };

    const int NC = K / MM_BKH;   // 32
    issue(0, 0); CP_COMMIT();
    issue(1, 1); CP_COMMIT();

    float acc[4][4][4] = {};

    for (int c = 0; c < NC; c++) {
        CP_WAIT1();
        __syncthreads();
        if (c + 2 < NC) issue(c + 2, (c + 2) % MM_STAGES);
        CP_COMMIT();

        const uint32_t* As = sm_u + (c % MM_STAGES) * MM_STAGE_W;
        const uint32_t* Bs = As + MM_TILE_W;
        #pragma unroll
        for (int ks = 0; ks < 4; ks++) {           // 4 ksteps of k16
            const int k0 = ks * 8;                 // word offset
            uint32_t af[4][4], bf[4][2];
            #pragma unroll
            for (int mt = 0; mt < 4; mt++) {
                const int row = wm + mt * 16;
                af[mt][0] = As[(row + g) * MM_STRW + k0 + tig];
                af[mt][1] = As[(row + g + 8) * MM_STRW + k0 + tig];
                af[mt][2] = As[(row + g) * MM_STRW + k0 + tig + 4];
                af[mt][3] = As[(row + g + 8) * MM_STRW + k0 + tig + 4];
            }
            #pragma unroll
            for (int nt = 0; nt < 4; nt++) {
                const int col = wn + nt * 8 + g;
                bf[nt][0] = Bs[col * MM_STRW + k0 + tig];
                bf[nt][1] = Bs[col * MM_STRW + k0 + tig + 4];
            }
            #pragma unroll
            for (int mt = 0; mt < 4; mt++)
                #pragma unroll
                for (int nt = 0; nt < 4; nt++)
                    mma_f16(acc[mt][nt], af[mt], bf[nt]);
        }
    }

    #pragma unroll
    for (int mt = 0; mt < 4; mt++) {
        const int row = m0 + wm + mt * 16 + g;
        #pragma unroll
        for (int nt = 0; nt < 4; nt++) {
            const int col = n0 + wn + nt * 8 + tig * 2;
            *(float2*)(C + (size_t)row * N + col) =
                make_float2(acc[mt][nt][0], acc[mt][nt][1]);
            *(float2*)(C + (size_t)(row + 8) * N + col) =
                make_float2(acc[mt][nt][2], acc[mt][nt][3]);
        }
    }
}

// ---------------------------------------------------------------------------
// RoPE + convert to half: reads fp32 (ld_in), writes half (ld_out), scaled.
// ---------------------------------------------------------------------------
__global__ void rope_cvt_kernel(const float* __restrict__ in, __half* __restrict__ out,
                                const float* __restrict__ freqs,
                                int nheads, int ld_in, int ld_out,
                                int total_pairs, float scale)
{
    int idx = blockIdx.x * blockDim.x + threadIdx.x;
    if (idx >= total_pairs) return;
    const int ppr = nheads * (HDIM / 2);
    int row = idx / ppr;
    int pr  = idx % ppr;
    int hh  = pr / (HDIM / 2);
    int i   = pr % (HDIM / 2);
    int s   = row % SEQ;
    float c  = freqs[s * HDIM + i * 2 + 0];
    float sn = freqs[s * HDIM + i * 2 + 1];
    const float* p = in + (size_t)row * ld_in + hh * HDIM + i * 2;
    float xr = p[0], xi = p[1];
    __half2 h = __floats2half2_rn((xr * c - xi * sn) * scale,
                                  (xr * sn + xi * c) * scale);
    *(__half2*)(out + (size_t)row * ld_out + hh * HDIM + i * 2) = h;
}

// ---------------------------------------------------------------------------
// FlashAttention-2 on fp16 mma.sync (fp32 accumulate), cp.async K/V buffers.
// CTA = 128 queries x one (b,h); 8 warps x 16 rows; K tiles of 64.
// Q (pre-scaled by 0.125*log2e, half), K half [4096,256], V^T half [256,4096].
// Smem (words): Q/K region 4608, V 4608, P 4608 -> 55296 B, 2 CTAs/SM.
// ---------------------------------------------------------------------------
#define FA_QT 128
#define FA_KT 64
#define FA_THREADS 256
#define FA_STRW 36                          // words per row everywhere
#define FA_KTILE_W (FA_KT * FA_STRW)        // 2304
#define FA_VW  4608
#define FA_PW  9216
#define FA_SMEM_W 13824
#define FA_SMEM_BYTES (FA_SMEM_W * 4)       // 55296

__global__ __launch_bounds__(FA_THREADS, 2)
void fa_kernel(const __half* __restrict__ Q,
               const __half* __restrict__ K,
               const __half* __restrict__ Vt,
               __half* __restrict__ O)
{
    extern __shared__ uint32_t smf[];
    uint32_t* Qs = smf;            // 128x36 words; later K double buffer (2x2304)
    uint32_t* Vs = smf + FA_VW;    // V^T double buffer (2x2304)
    uint32_t* Ps = smf + FA_PW;    // P 128x36 words
    const uint32_t sbase = smem_u32(smf);

    const int tid  = threadIdx.x;
    const int warp = tid >> 5;
    const int lane = tid & 31;
    const int g    = lane >> 2;
    const int tig  = lane & 3;

    const int qt = (gridDim.x - 1) - blockIdx.x;   // heavy tiles first
    const int h  = blockIdx.y;
    const int b  = blockIdx.z;
    const int kvh = h / GQA_REP;

    const int qrow0 = qt * FA_QT;
    const int wrow  = warp * 16;

    // --- load Q tile (raw half bits; 128 rows x 32 words)
    {
        const __half* Qg = Q + (size_t)(b * SEQ + qrow0) * (NHEADS * HDIM) + h * HDIM;
        #pragma unroll
        for (int it = 0; it < 4; it++) {
            int idx = tid + it * FA_THREADS;     // 0..1023
            int r = idx >> 3, c = idx & 7;
            *(uint4*)(Qs + r * FA_STRW + c * 4) =
                *(const uint4*)(Qg + (size_t)r * (NHEADS * HDIM) + c * 8);
        }
    }
    __syncthreads();

    // --- hoist Q fragments (4 ksteps of k16)
    uint32_t qf[4][4];
    #pragma unroll
    for (int ks = 0; ks < 4; ks++) {
        qf[ks][0] = Qs[(wrow + g) * FA_STRW + ks * 8 + tig];
        qf[ks][1] = Qs[(wrow + g + 8) * FA_STRW + ks * 8 + tig];
        qf[ks][2] = Qs[(wrow + g) * FA_STRW + ks * 8 + tig + 4];
        qf[ks][3] = Qs[(wrow + g + 8) * FA_STRW + ks * 8 + tig + 4];
    }
    __syncthreads();   // Q region becomes K double buffer

    const __half* Kb0 = K + (size_t)(b * SEQ) * (NKVH * HDIM) + kvh * HDIM;
    const __half* Vb0 = Vt + (size_t)(kvh * HDIM) * MROWS + b * SEQ;

    auto issue = [&](int kt_, int slot) {
        #pragma unroll
        for (int it = 0; it < 2; it++) {
            int idx = tid + it * FA_THREADS;   // 0..511
            int r = idx >> 3, c = idx & 7;
            // K tile: 64 key rows x 64 d halfs
            cp16(sbase + 4u * (slot * FA_KTILE_W + r * FA_STRW + c * 4),
                 Kb0 + (size_t)(kt_ * FA_KT + r) * (NKVH * HDIM) + c * 8);
            // V^T tile: 64 d rows x 64 key halfs
            cp16(sbase + 4u * (FA_VW + slot * FA_KTILE_W + r * FA_STRW + c * 4),
                 Vb0 + (size_t)r * MROWS + kt_ * FA_KT + c * 8);
        }
    };

    const int nkt = 2 * qt + 2;
    issue(0, 0); CP_COMMIT();
    issue(1, 1); CP_COMMIT();

    float m0r = -1e30f, m1r = -1e30f;
    float l0r = 0.0f,  l1r = 0.0f;
    float o[8][4] = {};

    for (int kt = 0; kt < nkt; kt++) {
        CP_WAIT1();
        __syncthreads();

        const uint32_t* Kw = Qs + (kt & 1) * FA_KTILE_W;
        const uint32_t* Vw = Vs + (kt & 1) * FA_KTILE_W;

        const bool active = (kt * FA_KT <= qrow0 + wrow + 15);
        if (active) {
            // S = Q K^T
            float s[8][4] = {};
            #pragma unroll
            for (int ks = 0; ks < 4; ks++) {
                #pragma unroll
                for (int nt = 0; nt < 8; nt++) {
                    uint32_t bf[2];
                    bf[0] = Kw[(nt * 8 + g) * FA_STRW + ks * 8 + tig];
                    bf[1] = Kw[(nt * 8 + g) * FA_STRW + ks * 8 + tig + 4];
                    mma_f16(s[nt], qf[ks], bf);
                }
            }

            // causal mask on diagonal-straddling tiles
            if (kt * FA_KT + (FA_KT - 1) > qrow0 + wrow) {
                const int rg  = qrow0 + wrow + g;
                const int rg8 = rg + 8;
                #pragma unroll
                for (int nt = 0; nt < 8; nt++) {
                    const int c0 = kt * FA_KT + nt * 8 + 2 * tig;
                    const int c1 = c0 + 1;
                    if (c0 > rg)  s[nt][0] = -1e30f;
                    if (c1 > rg)  s[nt][1] = -1e30f;
                    if (c0 > rg8) s[nt][2] = -1e30f;
                    if (c1 > rg8) s[nt][3] = -1e30f;
                }
            }

            // online softmax (log2 domain)
            float mx0 = -1e30f, mx1 = -1e30f;
            #pragma unroll
            for (int nt = 0; nt < 8; nt++) {
                mx0 = fmaxf(mx0, fmaxf(s[nt][0], s[nt][1]));
                mx1 = fmaxf(mx1, fmaxf(s[nt][2], s[nt][3]));
            }
            mx0 = fmaxf(mx0, __shfl_xor_sync(0xffffffffu, mx0, 1));
            mx0 = fmaxf(mx0, __shfl_xor_sync(0xffffffffu, mx0, 2));
            mx1 = fmaxf(mx1, __shfl_xor_sync(0xffffffffu, mx1, 1));
            mx1 = fmaxf(mx1, __shfl_xor_sync(0xffffffffu, mx1, 2));

            const float mn0 = fmaxf(m0r, mx0);
            const float mn1 = fmaxf(m1r, mx1);
            const float al0 = fexp2(m0r - mn0);
            const float al1 = fexp2(m1r - mn1);
            m0r = mn0; m1r = mn1;

            float sum0 = 0.0f, sum1 = 0.0f;
            uint32_t* Pw  = Ps + (wrow + g) * FA_STRW;
            uint32_t* Pw8 = Ps + (wrow + g + 8) * FA_STRW;
            #pragma unroll
            for (int nt = 0; nt < 8; nt++) {
                float p0 = fexp2(s[nt][0] - mn0);
                float p1 = fexp2(s[nt][1] - mn0);
                float p2 = fexp2(s[nt][2] - mn1);
                float p3 = fexp2(s[nt][3] - mn1);
                sum0 += p0 + p1;
                sum1 += p2 + p3;
                Pw[nt * 4 + tig]  = packh2(p0, p1);
                Pw8[nt * 4 + tig] = packh2(p2, p3);
            }
            sum0 += __shfl_xor_sync(0xffffffffu, sum0, 1);
            sum0 += __shfl_xor_sync(0xffffffffu, sum0, 2);
            sum1 += __shfl_xor_sync(0xffffffffu, sum1, 1);
            sum1 += __shfl_xor_sync(0xffffffffu, sum1, 2);
            l0r = l0r * al0 + sum0;
            l1r = l1r * al1 + sum1;

            #pragma unroll
            for (int nt = 0; nt < 8; nt++) {
                o[nt][0] *= al0; o[nt][1] *= al0;
                o[nt][2] *= al1; o[nt][3] *= al1;
            }
            __syncwarp();

            // O += P V  (P warp-private in smem; V^T shared)
            #pragma unroll
            for (int ks = 0; ks < 4; ks++) {
                uint32_t a[4];
                a[0] = Ps[(wrow + g) * FA_STRW + ks * 8 + tig];
                a[1] = Ps[(wrow + g + 8) * FA_STRW + ks * 8 + tig];
                a[2] = Ps[(wrow + g) * FA_STRW + ks * 8 + tig + 4];
                a[3] = Ps[(wrow + g + 8) * FA_STRW + ks * 8 + tig + 4];
                #pragma unroll
                for (int nt = 0; nt < 8; nt++) {
                    uint32_t bf[2];
                    bf[0] = Vw[(nt * 8 + g) * FA_STRW + ks * 8 + tig];
                    bf[1] = Vw[(nt * 8 + g) * FA_STRW + ks * 8 + tig + 4];
                    mma_f16(o[nt], a, bf);
                }
            }
        }
        __syncthreads();
        if (kt + 2 < nkt) issue(kt + 2, kt & 1);
        CP_COMMIT();
    }

    // epilogue: normalize, write half (feeds wo GEMM)
    const float il0 = 1.0f / l0r;
    const float il1 = 1.0f / l1r;
    __half* Ob = O + (size_t)(b * SEQ + qrow0 + wrow) * (NHEADS * HDIM) + h * HDIM;
    #pragma unroll
    for (int nt = 0; nt < 8; nt++) {
        *(__half2*)(Ob + (size_t)g * (NHEADS * HDIM) + nt * 8 + 2 * tig) =
            __floats2half2_rn(o[nt][0] * il0, o[nt][1] * il0);
        *(__half2*)(Ob + (size_t)(g + 8) * (NHEADS * HDIM) + nt * 8 + 2 * tig) =
            __floats2half2_rn(o[nt][2] * il1, o[nt][3] * il1);
    }
}

// ---------------------------------------------------------------------------
// launch
// ---------------------------------------------------------------------------
extern "C" void kernel_launch(void* const* d_in, const int* in_sizes, int n_in,
                              void* d_out, int out_size)
{
    const float* x     = (const float*)d_in[0];
    const float* freqs = (const float*)d_in[1];
    // d_in[2] is the additive mask — exactly causal; handled in-kernel.
    const float* wq    = (const float*)d_in[3];
    const float* wk    = (const float*)d_in[4];
    const float* wv    = (const float*)d_in[5];
    const float* wo    = (const float*)d_in[6];
    float* out = (float*)d_out;

    static __half *xh = nullptr, *qh = nullptr, *kh = nullptr, *vt = nullptr, *aoh = nullptr;
    static __half *wqTh = nullptr, *wkvTh = nullptr, *woTh = nullptr;
    static float *q32 = nullptr, *kv32 = nullptr;
    if (!xh) {
        cudaGetSymbolAddress((void**)&xh,    g_xh);
        cudaGetSymbolAddress((void**)&q32,   g_q);
        cudaGetSymbolAddress((void**)&qh,    g_qh);
        cudaGetSymbolAddress((void**)&kv32,  g_kv);
        cudaGetSymbolAddress((void**)&kh,    g_kh);
        cudaGetSymbolAddress((void**)&vt,    g_vt);
        cudaGetSymbolAddress((void**)&aoh,   g_aoh);
        cudaGetSymbolAddress((void**)&wqTh,  g_wqTh);
        cudaGetSymbolAddress((void**)&wkvTh, g_wkvTh);
        cudaGetSymbolAddress((void**)&woTh,  g_woTh);
        cudaFuncSetAttribute(mma_gemm_f16_kernel, cudaFuncAttributeMaxDynamicSharedMemorySize,
                             MM_SMEM_BYTES);
        cudaFuncSetAttribute(fa_kernel, cudaFuncAttributeMaxDynamicSharedMemorySize,
                             FA_SMEM_BYTES);
    }

    // convert x; transpose weights (to half, k-major)
    cvt_half_kernel<<<(MROWS * DMODEL / 8 + 255) / 256, 256>>>(x, xh, MROWS * DMODEL / 8);
    {
        dim3 blk(32, 8);
        transpose_w_kernel<<<dim3(64, 64), blk>>>(wq, wqTh, DMODEL, DMODEL);
        transpose_w_kernel<<<dim3(8, 64), blk>>>(wk, wkvTh, DMODEL, NKVH * HDIM);
        transpose_w_kernel<<<dim3(8, 64), blk>>>(
            wv, wkvTh + (size_t)(NKVH * HDIM) * DMODEL, DMODEL, NKVH * HDIM);
        transpose_w_kernel<<<dim3(64, 64), blk>>>(wo, woTh, DMODEL, DMODEL);
    }

    // projections (fp16 mma, fp32 out)
    mma_gemm_f16_kernel<<<dim3(DMODEL / MM_BN, MROWS / MM_BM), MM_THREADS, MM_SMEM_BYTES>>>(
        MROWS, DMODEL, DMODEL, xh, wqTh, q32);
    mma_gemm_f16_kernel<<<dim3(KVLD / MM_BN, MROWS / MM_BM), MM_THREADS, MM_SMEM_BYTES>>>(
        MROWS, KVLD, DMODEL, xh, wkvTh, kv32);

    // RoPE + half conversion: Q (scale folded), K; V transpose to half
    {
        const float qscale = 0.18033688011112042f;  // 0.125 * log2(e)
        int pq = MROWS * NHEADS * (HDIM / 2);
        int pk = MROWS * NKVH * (HDIM / 2);
        rope_cvt_kernel<<<(pq + 255) / 256, 256>>>(q32, qh, freqs, NHEADS,
                                                   NHEADS * HDIM, NHEADS * HDIM, pq, qscale);
        rope_cvt_kernel<<<(pk + 255) / 256, 256>>>(kv32, kh, freqs, NKVH,
                                                   KVLD, NKVH * HDIM, pk, 1.0f);
        transpose_v_kernel<<<dim3(8, 128), dim3(32, 8)>>>(kv32, vt);
    }

    // attention
    fa_kernel<<<dim3(SEQ / FA_QT, NHEADS, BATCH), FA_THREADS, FA_SMEM_BYTES>>>(qh, kh, vt, aoh);

    // output projection (fp32 epilogue straight to d_out)
    mma_gemm_f16_kernel<<<dim3(DMODEL / MM_BN, MROWS / MM_BM), MM_THREADS, MM_SMEM_BYTES>>>(
        MROWS, DMODEL, DMODEL, aoh, woTh, out);
}

// round 8
// speedup vs baseline: 8.4298x; 1.0396x over previous
#include <cuda_runtime.h>
#include <cuda_fp16.h>
#include <math.h>
#include <stdint.h>

// Problem constants
#define BATCH 2
#define SEQ   2048
#define DMODEL 2048
#define NHEADS 32
#define NKVH   4
#define HDIM   64
#define GQA_REP (NHEADS / NKVH)   // 8
#define MROWS (BATCH * SEQ)       // 4096
#define KVN   (2 * NKVH * HDIM)   // 512: fused [K|V] gemm N

// Scratch (device globals; no runtime allocation allowed)
__device__ __half g_xh[MROWS * DMODEL];
__device__ __half g_qh[MROWS * NHEADS * HDIM];   // rope'd, scaled, half
__device__ __half g_kh[MROWS * NKVH * HDIM];     // rope'd K half [4096,256]
__device__ __half g_vh[MROWS * NKVH * HDIM];     // V half [4096,256]
__device__ __half g_vt[NKVH * HDIM * MROWS];     // V^T half [256,4096]
__device__ __half g_aoh[MROWS * NHEADS * HDIM];  // attention out, half
__device__ __half g_wqTh[DMODEL * DMODEL];       // (N,K) k-major half
__device__ __half g_wkvTh[KVN * DMODEL];
__device__ __half g_woTh[DMODEL * DMODEL];

// ---------------------------------------------------------------------------
// helpers
// ---------------------------------------------------------------------------
__device__ __forceinline__ uint32_t smem_u32(const void* p) {
    uint32_t a;
    asm("{ .reg .u64 t; cvta.to.shared.u64 t, %1; cvt.u32.u64 %0, t; }"
        : "=r"(a) : "l"(p));
    return a;
}
__device__ __forceinline__ float fexp2(float x) {
    float y;
    asm("ex2.approx.ftz.f32 %0, %1;" : "=f"(y) : "f"(x));
    return y;
}
__device__ __forceinline__ uint32_t packh2(float lo, float hi) {
    __half2 h = __floats2half2_rn(lo, hi);
    return *reinterpret_cast<uint32_t*>(&h);
}
__device__ __forceinline__ void mma_f16(float* d, const uint32_t* a, const uint32_t* b) {
    asm volatile(
        "mma.sync.aligned.m16n8k16.row.col.f32.f16.f16.f32 "
        "{%0,%1,%2,%3}, {%4,%5,%6,%7}, {%8,%9}, {%0,%1,%2,%3};"
        : "+f"(d[0]), "+f"(d[1]), "+f"(d[2]), "+f"(d[3])
        : "r"(a[0]), "r"(a[1]), "r"(a[2]), "r"(a[3]), "r"(b[0]), "r"(b[1]));
}
__device__ __forceinline__ void cp16(uint32_t saddr, const void* g) {
    asm volatile("cp.async.cg.shared.global [%0], [%1], 16;" :: "r"(saddr), "l"(g));
}
#define CP_COMMIT() asm volatile("cp.async.commit_group;" ::: "memory")
#define CP_WAIT1()  asm volatile("cp.async.wait_group 1;" ::: "memory")

// ---------------------------------------------------------------------------
// x (fp32) -> half
// ---------------------------------------------------------------------------
__global__ void cvt_half_kernel(const float* __restrict__ in, __half* __restrict__ out,
                                int n8)
{
    int i = blockIdx.x * blockDim.x + threadIdx.x;
    if (i >= n8) return;
    float4 a = ((const float4*)in)[2 * i];
    float4 b = ((const float4*)in)[2 * i + 1];
    uint4 u = make_uint4(packh2(a.x, a.y), packh2(a.z, a.w),
                         packh2(b.x, b.y), packh2(b.z, b.w));
    ((uint4*)out)[i] = u;
}

// ---------------------------------------------------------------------------
// Weight transpose to half: in [R,C] fp32 -> out [C,R] half
// ---------------------------------------------------------------------------
__global__ void transpose_w_kernel(const float* __restrict__ in, __half* __restrict__ out,
                                   int R, int C)
{
    __shared__ float t[32][33];
    int c0 = blockIdx.x * 32, r0 = blockIdx.y * 32;
    int x = threadIdx.x, y = threadIdx.y;  // 32 x 8
    #pragma unroll
    for (int j = 0; j < 4; j++)
        t[y + 8 * j][x] = in[(size_t)(r0 + y + 8 * j) * C + c0 + x];
    __syncthreads();
    #pragma unroll
    for (int j = 0; j < 4; j++)
        out[(size_t)(c0 + y + 8 * j) * R + r0 + x] = __float2half_rn(t[x][y + 8 * j]);
}

// V transpose (half -> half): vh [4096, 256] -> vt [256, 4096]
__global__ void transpose_vh_kernel(const __half* __restrict__ vh, __half* __restrict__ vt)
{
    __shared__ float t[32][33];
    int c0 = blockIdx.x * 32;   // d (0..255)
    int r0 = blockIdx.y * 32;   // seq row
    int x = threadIdx.x, y = threadIdx.y;
    #pragma unroll
    for (int j = 0; j < 4; j++)
        t[y + 8 * j][x] = __half2float(vh[(size_t)(r0 + y + 8 * j) * (NKVH * HDIM) + c0 + x]);
    __syncthreads();
    #pragma unroll
    for (int j = 0; j < 4; j++)
        vt[(size_t)(c0 + y + 8 * j) * MROWS + r0 + x] = __float2half_rn(t[x][y + 8 * j]);
}

// ---------------------------------------------------------------------------
// fp16 mma.sync GEMM: CTA 128x128, 4 warps (2x2), warp tile 64x64, BK=64 halfs.
// 3-stage cp.async pipeline. Smem rows 32 words + 4 pad (stride 36; LDS bank
// = 4g+tig, conflict-free).
// Epilogue modes: 0 = fp32 C; 1 = rope+scale -> half Q (ld 2048);
//                 2 = rope K (ld 256) / plain V (ld 256).
// ---------------------------------------------------------------------------
#define MM_BM 128
#define MM_BN 128
#define MM_BKH 64
#define MM_STRW 36
#define MM_THREADS 128
#define MM_TILE_W (MM_BM * MM_STRW)            // 4608 words
#define MM_STAGE_W (2 * MM_TILE_W)             // 9216
#define MM_STAGES 3
#define MM_SMEM_BYTES (MM_STAGES * MM_STAGE_W * 4)   // 110592

__global__ __launch_bounds__(MM_THREADS)
void mma_gemm_f16_kernel(int M, int N, int K,
                         const __half* __restrict__ A,
                         const __half* __restrict__ BT,
                         float* __restrict__ C,
                         __half* __restrict__ Hout0,   // mode1: qh; mode2: kh
                         __half* __restrict__ Hout1,   // mode2: vh
                         const float* __restrict__ freqs,
                         int mode, float scale)
{
    extern __shared__ uint32_t sm_u[];
    const uint32_t sbase = smem_u32(sm_u);

    const int tid  = threadIdx.x;
    const int warp = tid >> 5;
    const int lane = tid & 31;
    const int g    = lane >> 2;
    const int tig  = lane & 3;

    const int wm = (warp >> 1) * 64;   // 0 or 64
    const int wn = (warp & 1) * 64;    // 0 or 64

    const int m0 = blockIdx.y * MM_BM;
    const int n0 = blockIdx.x * MM_BN;

    // loader: 2048 cp16 per chunk / 128 threads = 16 each (8 A + 8 B)
    const int lr = tid >> 3;        // 0..15
    const int lc = tid & 7;         // 0..7

    auto issue = [&](int c, int slot) {
        const uint32_t sa = sbase + 4u * (slot * MM_STAGE_W);
        #pragma unroll
        for (int j = 0; j < 8; j++) {
            int r = lr + j * 16;
            cp16(sa + 4u * (r * MM_STRW + lc * 4),
                 A + (size_t)(m0 + r) * K + c * MM_BKH + lc * 8);
            cp16(sa + 4u * (MM_TILE_W + r * MM_STRW + lc * 4),
                 BT + (size_t)(n0 + r) * K + c * MM_BKH + lc * 8);
        }
    };

    const int NC = K / MM_BKH;   // 32
    issue(0, 0); CP_COMMIT();
    issue(1, 1); CP_COMMIT();

    float acc[4][8][4] = {};

    for (int c = 0; c < NC; c++) {
        CP_WAIT1();
        __syncthreads();
        if (c + 2 < NC) issue(c + 2, (c + 2) % MM_STAGES);
        CP_COMMIT();

        const uint32_t* As = sm_u + (c % MM_STAGES) * MM_STAGE_W;
        const uint32_t* Bs = As + MM_TILE_W;
        #pragma unroll
        for (int ks = 0; ks < 4; ks++) {           // 4 ksteps of k16
            const int k0 = ks * 8;
            uint32_t af[4][4], bf[8][2];
            #pragma unroll
            for (int mt = 0; mt < 4; mt++) {
                const int row = wm + mt * 16;
                af[mt][0] = As[(row + g) * MM_STRW + k0 + tig];
                af[mt][1] = As[(row + g + 8) * MM_STRW + k0 + tig];
                af[mt][2] = As[(row + g) * MM_STRW + k0 + tig + 4];
                af[mt][3] = As[(row + g + 8) * MM_STRW + k0 + tig + 4];
            }
            #pragma unroll
            for (int nt = 0; nt < 8; nt++) {
                const int col = wn + nt * 8 + g;
                bf[nt][0] = Bs[col * MM_STRW + k0 + tig];
                bf[nt][1] = Bs[col * MM_STRW + k0 + tig + 4];
            }
            #pragma unroll
            for (int mt = 0; mt < 4; mt++)
                #pragma unroll
                for (int nt = 0; nt < 8; nt++)
                    mma_f16(acc[mt][nt], af[mt], bf[nt]);
        }
    }

    // ---- epilogue
    if (mode == 0) {
        #pragma unroll
        for (int mt = 0; mt < 4; mt++) {
            const int row = m0 + wm + mt * 16 + g;
            #pragma unroll
            for (int nt = 0; nt < 8; nt++) {
                const int col = n0 + wn + nt * 8 + tig * 2;
                *(float2*)(C + (size_t)row * N + col) =
                    make_float2(acc[mt][nt][0], acc[mt][nt][1]);
                *(float2*)(C + (size_t)(row + 8) * N + col) =
                    make_float2(acc[mt][nt][2], acc[mt][nt][3]);
            }
        }
    } else if (mode == 1 || (mode == 2 && n0 < NKVH * HDIM)) {
        // rope + scale -> half (Q: ld 2048, or K: ld 256)
        __half* Out = Hout0;
        const int ldo = (mode == 1) ? N : (NKVH * HDIM);
        #pragma unroll
        for (int mt = 0; mt < 4; mt++) {
            const int row = m0 + wm + mt * 16 + g;
            const int s0 = row & (SEQ - 1);
            const int s1 = (row + 8) & (SEQ - 1);
            #pragma unroll
            for (int nt = 0; nt < 8; nt++) {
                const int col = n0 + wn + nt * 8 + tig * 2;
                const int i = (col & 63) >> 1;
                float2 cs0 = *(const float2*)(freqs + s0 * HDIM + i * 2);
                float2 cs1 = *(const float2*)(freqs + s1 * HDIM + i * 2);
                float xr = acc[mt][nt][0], xi = acc[mt][nt][1];
                *(uint32_t*)(Out + (size_t)row * ldo + col) =
                    packh2((xr * cs0.x - xi * cs0.y) * scale,
                           (xr * cs0.y + xi * cs0.x) * scale);
                xr = acc[mt][nt][2]; xi = acc[mt][nt][3];
                *(uint32_t*)(Out + (size_t)(row + 8) * ldo + col) =
                    packh2((xr * cs1.x - xi * cs1.y) * scale,
                           (xr * cs1.y + xi * cs1.x) * scale);
            }
        }
    } else {
        // V columns: plain half, col-256 into vh [4096,256]
        __half* Out = Hout1;
        #pragma unroll
        for (int mt = 0; mt < 4; mt++) {
            const int row = m0 + wm + mt * 16 + g;
            #pragma unroll
            for (int nt = 0; nt < 8; nt++) {
                const int col = n0 + wn + nt * 8 + tig * 2 - NKVH * HDIM;
                *(uint32_t*)(Out + (size_t)row * (NKVH * HDIM) + col) =
                    packh2(acc[mt][nt][0], acc[mt][nt][1]);
                *(uint32_t*)(Out + (size_t)(row + 8) * (NKVH * HDIM) + col) =
                    packh2(acc[mt][nt][2], acc[mt][nt][3]);
            }
        }
    }
}

// ---------------------------------------------------------------------------
// FlashAttention-2 on fp16 mma.sync (fp32 accumulate), cp.async K/V buffers.
// Unchanged from round 6 (passing).
// ---------------------------------------------------------------------------
#define FA_QT 128
#define FA_KT 64
#define FA_THREADS 256
#define FA_STRW 36
#define FA_KTILE_W (FA_KT * FA_STRW)        // 2304
#define FA_VW  4608
#define FA_PW  9216
#define FA_SMEM_W 13824
#define FA_SMEM_BYTES (FA_SMEM_W * 4)       // 55296

__global__ __launch_bounds__(FA_THREADS, 2)
void fa_kernel(const __half* __restrict__ Q,
               const __half* __restrict__ K,
               const __half* __restrict__ Vt,
               __half* __restrict__ O)
{
    extern __shared__ uint32_t smf[];
    uint32_t* Qs = smf;
    uint32_t* Vs = smf + FA_VW;
    uint32_t* Ps = smf + FA_PW;
    const uint32_t sbase = smem_u32(smf);

    const int tid  = threadIdx.x;
    const int warp = tid >> 5;
    const int lane = tid & 31;
    const int g    = lane >> 2;
    const int tig  = lane & 3;

    const int qt = (gridDim.x - 1) - blockIdx.x;
    const int h  = blockIdx.y;
    const int b  = blockIdx.z;
    const int kvh = h / GQA_REP;

    const int qrow0 = qt * FA_QT;
    const int wrow  = warp * 16;

    {
        const __half* Qg = Q + (size_t)(b * SEQ + qrow0) * (NHEADS * HDIM) + h * HDIM;
        #pragma unroll
        for (int it = 0; it < 4; it++) {
            int idx = tid + it * FA_THREADS;
            int r = idx >> 3, c = idx & 7;
            *(uint4*)(Qs + r * FA_STRW + c * 4) =
                *(const uint4*)(Qg + (size_t)r * (NHEADS * HDIM) + c * 8);
        }
    }
    __syncthreads();

    uint32_t qf[4][4];
    #pragma unroll
    for (int ks = 0; ks < 4; ks++) {
        qf[ks][0] = Qs[(wrow + g) * FA_STRW + ks * 8 + tig];
        qf[ks][1] = Qs[(wrow + g + 8) * FA_STRW + ks * 8 + tig];
        qf[ks][2] = Qs[(wrow + g) * FA_STRW + ks * 8 + tig + 4];
        qf[ks][3] = Qs[(wrow + g + 8) * FA_STRW + ks * 8 + tig + 4];
    }
    __syncthreads();

    const __half* Kb0 = K + (size_t)(b * SEQ) * (NKVH * HDIM) + kvh * HDIM;
    const __half* Vb0 = Vt + (size_t)(kvh * HDIM) * MROWS + b * SEQ;

    auto issue = [&](int kt_, int slot) {
        #pragma unroll
        for (int it = 0; it < 2; it++) {
            int idx = tid + it * FA_THREADS;
            int r = idx >> 3, c = idx & 7;
            cp16(sbase + 4u * (slot * FA_KTILE_W + r * FA_STRW + c * 4),
                 Kb0 + (size_t)(kt_ * FA_KT + r) * (NKVH * HDIM) + c * 8);
            cp16(sbase + 4u * (FA_VW + slot * FA_KTILE_W + r * FA_STRW + c * 4),
                 Vb0 + (size_t)r * MROWS + kt_ * FA_KT + c * 8);
        }
    };

    const int nkt = 2 * qt + 2;
    issue(0, 0); CP_COMMIT();
    issue(1, 1); CP_COMMIT();

    float m0r = -1e30f, m1r = -1e30f;
    float l0r = 0.0f,  l1r = 0.0f;
    float o[8][4] = {};

    for (int kt = 0; kt < nkt; kt++) {
        CP_WAIT1();
        __syncthreads();

        const uint32_t* Kw = Qs + (kt & 1) * FA_KTILE_W;
        const uint32_t* Vw = Vs + (kt & 1) * FA_KTILE_W;

        const bool active = (kt * FA_KT <= qrow0 + wrow + 15);
        if (active) {
            float s[8][4] = {};
            #pragma unroll
            for (int ks = 0; ks < 4; ks++) {
                #pragma unroll
                for (int nt = 0; nt < 8; nt++) {
                    uint32_t bf[2];
                    bf[0] = Kw[(nt * 8 + g) * FA_STRW + ks * 8 + tig];
                    bf[1] = Kw[(nt * 8 + g) * FA_STRW + ks * 8 + tig + 4];
                    mma_f16(s[nt], qf[ks], bf);
                }
            }

            if (kt * FA_KT + (FA_KT - 1) > qrow0 + wrow) {
                const int rg  = qrow0 + wrow + g;
                const int rg8 = rg + 8;
                #pragma unroll
                for (int nt = 0; nt < 8; nt++) {
                    const int c0 = kt * FA_KT + nt * 8 + 2 * tig;
                    const int c1 = c0 + 1;
                    if (c0 > rg)  s[nt][0] = -1e30f;
                    if (c1 > rg)  s[nt][1] = -1e30f;
                    if (c0 > rg8) s[nt][2] = -1e30f;
                    if (c1 > rg8) s[nt][3] = -1e30f;
                }
            }

            float mx0 = -1e30f, mx1 = -1e30f;
            #pragma unroll
            for (int nt = 0; nt < 8; nt++) {
                mx0 = fmaxf(mx0, fmaxf(s[nt][0], s[nt][1]));
                mx1 = fmaxf(mx1, fmaxf(s[nt][2], s[nt][3]));
            }
            mx0 = fmaxf(mx0, __shfl_xor_sync(0xffffffffu, mx0, 1));
            mx0 = fmaxf(mx0, __shfl_xor_sync(0xffffffffu, mx0, 2));
            mx1 = fmaxf(mx1, __shfl_xor_sync(0xffffffffu, mx1, 1));
            mx1 = fmaxf(mx1, __shfl_xor_sync(0xffffffffu, mx1, 2));

            const float mn0 = fmaxf(m0r, mx0);
            const float mn1 = fmaxf(m1r, mx1);
            const float al0 = fexp2(m0r - mn0);
            const float al1 = fexp2(m1r - mn1);
            m0r = mn0; m1r = mn1;

            float sum0 = 0.0f, sum1 = 0.0f;
            uint32_t* Pw  = Ps + (wrow + g) * FA_STRW;
            uint32_t* Pw8 = Ps + (wrow + g + 8) * FA_STRW;
            #pragma unroll
            for (int nt = 0; nt < 8; nt++) {
                float p0 = fexp2(s[nt][0] - mn0);
                float p1 = fexp2(s[nt][1] - mn0);
                float p2 = fexp2(s[nt][2] - mn1);
                float p3 = fexp2(s[nt][3] - mn1);
                sum0 += p0 + p1;
                sum1 += p2 + p3;
                Pw[nt * 4 + tig]  = packh2(p0, p1);
                Pw8[nt * 4 + tig] = packh2(p2, p3);
            }
            sum0 += __shfl_xor_sync(0xffffffffu, sum0, 1);
            sum0 += __shfl_xor_sync(0xffffffffu, sum0, 2);
            sum1 += __shfl_xor_sync(0xffffffffu, sum1, 1);
            sum1 += __shfl_xor_sync(0xffffffffu, sum1, 2);
            l0r = l0r * al0 + sum0;
            l1r = l1r * al1 + sum1;

            #pragma unroll
            for (int nt = 0; nt < 8; nt++) {
                o[nt][0] *= al0; o[nt][1] *= al0;
                o[nt][2] *= al1; o[nt][3] *= al1;
            }
            __syncwarp();

            #pragma unroll
            for (int ks = 0; ks < 4; ks++) {
                uint32_t a[4];
                a[0] = Ps[(wrow + g) * FA_STRW + ks * 8 + tig];
                a[1] = Ps[(wrow + g + 8) * FA_STRW + ks * 8 + tig];
                a[2] = Ps[(wrow + g) * FA_STRW + ks * 8 + tig + 4];
                a[3] = Ps[(wrow + g + 8) * FA_STRW + ks * 8 + tig + 4];
                #pragma unroll
                for (int nt = 0; nt < 8; nt++) {
                    uint32_t bf[2];
                    bf[0] = Vw[(nt * 8 + g) * FA_STRW + ks * 8 + tig];
                    bf[1] = Vw[(nt * 8 + g) * FA_STRW + ks * 8 + tig + 4];
                    mma_f16(o[nt], a, bf);
                }
            }
        }
        __syncthreads();
        if (kt + 2 < nkt) issue(kt + 2, kt & 1);
        CP_COMMIT();
    }

    const float il0 = 1.0f / l0r;
    const float il1 = 1.0f / l1r;
    __half* Ob = O + (size_t)(b * SEQ + qrow0 + wrow) * (NHEADS * HDIM) + h * HDIM;
    #pragma unroll
    for (int nt = 0; nt < 8; nt++) {
        *(__half2*)(Ob + (size_t)g * (NHEADS * HDIM) + nt * 8 + 2 * tig) =
            __floats2half2_rn(o[nt][0] * il0, o[nt][1] * il0);
        *(__half2*)(Ob + (size_t)(g + 8) * (NHEADS * HDIM) + nt * 8 + 2 * tig) =
            __floats2half2_rn(o[nt][2] * il1, o[nt][3] * il1);
    }
}

// ---------------------------------------------------------------------------
// launch
// ---------------------------------------------------------------------------
extern "C" void kernel_launch(void* const* d_in, const int* in_sizes, int n_in,
                              void* d_out, int out_size)
{
    const float* x     = (const float*)d_in[0];
    const float* freqs = (const float*)d_in[1];
    // d_in[2] is the additive mask — exactly causal; handled in-kernel.
    const float* wq    = (const float*)d_in[3];
    const float* wk    = (const float*)d_in[4];
    const float* wv    = (const float*)d_in[5];
    const float* wo    = (const float*)d_in[6];
    float* out = (float*)d_out;

    static __half *xh = nullptr, *qh = nullptr, *kh = nullptr, *vh = nullptr,
                  *vt = nullptr, *aoh = nullptr;
    static __half *wqTh = nullptr, *wkvTh = nullptr, *woTh = nullptr;
    if (!xh) {
        cudaGetSymbolAddress((void**)&xh,    g_xh);
        cudaGetSymbolAddress((void**)&qh,    g_qh);
        cudaGetSymbolAddress((void**)&kh,    g_kh);
        cudaGetSymbolAddress((void**)&vh,    g_vh);
        cudaGetSymbolAddress((void**)&vt,    g_vt);
        cudaGetSymbolAddress((void**)&aoh,   g_aoh);
        cudaGetSymbolAddress((void**)&wqTh,  g_wqTh);
        cudaGetSymbolAddress((void**)&wkvTh, g_wkvTh);
        cudaGetSymbolAddress((void**)&woTh,  g_woTh);
        cudaFuncSetAttribute(mma_gemm_f16_kernel, cudaFuncAttributeMaxDynamicSharedMemorySize,
                             MM_SMEM_BYTES);
        cudaFuncSetAttribute(fa_kernel, cudaFuncAttributeMaxDynamicSharedMemorySize,
                             FA_SMEM_BYTES);
    }

    const float qscale = 0.18033688011112042f;  // 0.125 * log2(e)

    // convert x; transpose weights (to half, k-major)
    cvt_half_kernel<<<(MROWS * DMODEL / 8 + 255) / 256, 256>>>(x, xh, MROWS * DMODEL / 8);
    {
        dim3 blk(32, 8);
        transpose_w_kernel<<<dim3(64, 64), blk>>>(wq, wqTh, DMODEL, DMODEL);
        transpose_w_kernel<<<dim3(8, 64), blk>>>(wk, wkvTh, DMODEL, NKVH * HDIM);
        transpose_w_kernel<<<dim3(8, 64), blk>>>(
            wv, wkvTh + (size_t)(NKVH * HDIM) * DMODEL, DMODEL, NKVH * HDIM);
        transpose_w_kernel<<<dim3(64, 64), blk>>>(wo, woTh, DMODEL, DMODEL);
    }

    // Q projection with fused rope+scale -> qh (half)
    mma_gemm_f16_kernel<<<dim3(DMODEL / MM_BN, MROWS / MM_BM), MM_THREADS, MM_SMEM_BYTES>>>(
        MROWS, DMODEL, DMODEL, xh, wqTh, nullptr, qh, nullptr, freqs, 1, qscale);
    // KV projection: K gets rope -> kh, V plain -> vh
    mma_gemm_f16_kernel<<<dim3(KVN / MM_BN, MROWS / MM_BM), MM_THREADS, MM_SMEM_BYTES>>>(
        MROWS, KVN, DMODEL, xh, wkvTh, nullptr, kh, vh, freqs, 2, 1.0f);

    // V transpose (half->half)
    transpose_vh_kernel<<<dim3(8, 128), dim3(32, 8)>>>(vh, vt);

    // attention
    fa_kernel<<<dim3(SEQ / FA_QT, NHEADS, BATCH), FA_THREADS, FA_SMEM_BYTES>>>(qh, kh, vt, aoh);

    // output projection (fp32 epilogue straight to d_out)
    mma_gemm_f16_kernel<<<dim3(DMODEL / MM_BN, MROWS / MM_BM), MM_THREADS, MM_SMEM_BYTES>>>(
        MROWS, DMODEL, DMODEL, aoh, woTh, out, nullptr, nullptr, nullptr, 0, 1.0f);
}